// round 1
// baseline (speedup 1.0000x reference)
#include <cuda_runtime.h>
#include <cuda_bf16.h>
#include <mma.h>
#include <math.h>

using namespace nvcuda;

// Problem dims
constexpr int Bc  = 4;
constexpr int Lc  = 512;
constexpr int Dc  = 2048;
constexpr int Hc  = 16;
constexpr int Cc  = 128;
constexpr int KVc = 2048;
constexpr int Kc  = 1024;   // T*LA

// ---------------------------------------------------------------------------
// Scratch (device globals: allocation-free rule)
// ---------------------------------------------------------------------------
__device__ float g_xk[(size_t)Bc * Kc * KVc];          // 32 MB  LN(x)
__device__ float g_lat[(size_t)Bc * Lc * Dc];          // 16 MB  modulated LN(latents)
__device__ float g_q[(size_t)Bc * Lc * Dc];            // 16 MB
__device__ float g_kv[(size_t)Bc * Kc * 2 * Dc];       // 64 MB
__device__ float g_scores[(size_t)Bc * Hc * Lc * Kc];  // 128 MB
__device__ float g_attn[(size_t)Bc * Lc * Dc];         // 16 MB

// ---------------------------------------------------------------------------
// Reduction helpers (256-thread blocks)
// ---------------------------------------------------------------------------
__device__ __forceinline__ float warp_sum(float v) {
    #pragma unroll
    for (int o = 16; o > 0; o >>= 1) v += __shfl_xor_sync(0xffffffffu, v, o);
    return v;
}
__device__ __forceinline__ float warp_max(float v) {
    #pragma unroll
    for (int o = 16; o > 0; o >>= 1) v = fmaxf(v, __shfl_xor_sync(0xffffffffu, v, o));
    return v;
}
// red must have >= 33 floats. Safe for back-to-back calls (3 syncs).
__device__ __forceinline__ float block_sum256(float v, float* red) {
    int lane = threadIdx.x & 31, w = threadIdx.x >> 5;
    v = warp_sum(v);
    if (lane == 0) red[w] = v;
    __syncthreads();
    if (w == 0) {
        float t = (lane < 8) ? red[lane] : 0.0f;
        t = warp_sum(t);
        if (lane == 0) red[32] = t;
    }
    __syncthreads();
    float r = red[32];
    __syncthreads();
    return r;
}
__device__ __forceinline__ float block_max256(float v, float* red) {
    int lane = threadIdx.x & 31, w = threadIdx.x >> 5;
    v = warp_max(v);
    if (lane == 0) red[w] = v;
    __syncthreads();
    if (w == 0) {
        float t = (lane < 8) ? red[lane] : -1e30f;
        t = warp_max(t);
        if (lane == 0) red[32] = t;
    }
    __syncthreads();
    float r = red[32];
    __syncthreads();
    return r;
}

// ---------------------------------------------------------------------------
// LayerNorm of x -> xk   (rows = B*K, width = KV = 2048), 256 threads/row
// ---------------------------------------------------------------------------
__global__ void ln_x_kernel(const float* __restrict__ x,
                            const float* __restrict__ w,
                            const float* __restrict__ b,
                            float* __restrict__ out) {
    __shared__ float red[33];
    const int row = blockIdx.x;
    const size_t base = (size_t)row * KVc;
    const int t = threadIdx.x;
    const int c0 = t * 4;
    const int c1 = c0 + 1024;

    float4 v0 = *reinterpret_cast<const float4*>(&x[base + c0]);
    float4 v1 = *reinterpret_cast<const float4*>(&x[base + c1]);

    float s = v0.x + v0.y + v0.z + v0.w + v1.x + v1.y + v1.z + v1.w;
    float mean = block_sum256(s, red) * (1.0f / KVc);

    float d0x = v0.x - mean, d0y = v0.y - mean, d0z = v0.z - mean, d0w = v0.w - mean;
    float d1x = v1.x - mean, d1y = v1.y - mean, d1z = v1.z - mean, d1w = v1.w - mean;
    float sq = d0x*d0x + d0y*d0y + d0z*d0z + d0w*d0w + d1x*d1x + d1y*d1y + d1z*d1z + d1w*d1w;
    float var = block_sum256(sq, red) * (1.0f / KVc);
    float rstd = rsqrtf(var + 1e-5f);

    float4 w0 = *reinterpret_cast<const float4*>(&w[c0]);
    float4 w1 = *reinterpret_cast<const float4*>(&w[c1]);
    float4 b0 = *reinterpret_cast<const float4*>(&b[c0]);
    float4 b1 = *reinterpret_cast<const float4*>(&b[c1]);

    float4 o0 = make_float4(d0x*rstd*w0.x + b0.x, d0y*rstd*w0.y + b0.y,
                            d0z*rstd*w0.z + b0.z, d0w*rstd*w0.w + b0.w);
    float4 o1 = make_float4(d1x*rstd*w1.x + b1.x, d1y*rstd*w1.y + b1.y,
                            d1z*rstd*w1.z + b1.z, d1w*rstd*w1.w + b1.w);
    *reinterpret_cast<float4*>(&out[base + c0]) = o0;
    *reinterpret_cast<float4*>(&out[base + c1]) = o1;
}

// ---------------------------------------------------------------------------
// LayerNorm of latents + adaLN modulation -> lat
// lat = norm * (1 + scale[b]) + shift[b]; rows = B*L, width = D
// ---------------------------------------------------------------------------
__global__ void ln_lat_kernel(const float* __restrict__ latents,
                              const float* __restrict__ t_emb,
                              const float* __restrict__ ssg,
                              float* __restrict__ out) {
    __shared__ float red[33];
    const int row = blockIdx.x;
    const int bidx = row / Lc;
    const size_t base = (size_t)row * Dc;
    const int t = threadIdx.x;
    const int c0 = t * 4;
    const int c1 = c0 + 1024;

    float4 v0 = *reinterpret_cast<const float4*>(&latents[base + c0]);
    float4 v1 = *reinterpret_cast<const float4*>(&latents[base + c1]);

    float s = v0.x + v0.y + v0.z + v0.w + v1.x + v1.y + v1.z + v1.w;
    float mean = block_sum256(s, red) * (1.0f / Dc);

    float d0x = v0.x - mean, d0y = v0.y - mean, d0z = v0.z - mean, d0w = v0.w - mean;
    float d1x = v1.x - mean, d1y = v1.y - mean, d1z = v1.z - mean, d1w = v1.w - mean;
    float sq = d0x*d0x + d0y*d0y + d0z*d0z + d0w*d0w + d1x*d1x + d1y*d1y + d1z*d1z + d1w*d1w;
    float var = block_sum256(sq, red) * (1.0f / Dc);
    float rstd = rsqrtf(var + 1e-5f);

    const float* sh_t = t_emb + (size_t)(bidx * 3 + 0) * Dc;
    const float* sc_t = t_emb + (size_t)(bidx * 3 + 1) * Dc;
    const float* sh_s = ssg;
    const float* sc_s = ssg + Dc;

    #pragma unroll
    for (int half = 0; half < 2; half++) {
        int c = (half == 0) ? c0 : c1;
        float dv[4] = { (half ? d1x : d0x), (half ? d1y : d0y),
                        (half ? d1z : d0z), (half ? d1w : d0w) };
        float4 sht = *reinterpret_cast<const float4*>(&sh_t[c]);
        float4 sct = *reinterpret_cast<const float4*>(&sc_t[c]);
        float4 shs = *reinterpret_cast<const float4*>(&sh_s[c]);
        float4 scs = *reinterpret_cast<const float4*>(&sc_s[c]);
        float sc[4] = { sct.x + scs.x, sct.y + scs.y, sct.z + scs.z, sct.w + scs.w };
        float sh[4] = { sht.x + shs.x, sht.y + shs.y, sht.z + shs.z, sht.w + shs.w };
        float4 o;
        o.x = dv[0]*rstd * (1.0f + sc[0]) + sh[0];
        o.y = dv[1]*rstd * (1.0f + sc[1]) + sh[1];
        o.z = dv[2]*rstd * (1.0f + sc[2]) + sh[2];
        o.w = dv[3]*rstd * (1.0f + sc[3]) + sh[3];
        *reinterpret_cast<float4*>(&out[base + c]) = o;
    }
}

// ---------------------------------------------------------------------------
// bf16x3 split-compensated GEMM (wmma m16n16k16).
//   C = A @ B        (BCOL=false, B row-major KxN)
//   C = A @ B^T      (BCOL=true,  B stored row-major NxK, read col-major)
// Tile: 128x128x32, 256 threads, 8 warps (2x4), each warp 64x32 output.
// Batched via z: offset = (z/HB)*{a,b,c}sb + (z%HB)*{a,b,c}sh.
// Pure accumulate-store: epilogues (bias/alpha/gate) handled elsewhere.
// ---------------------------------------------------------------------------
template <bool BCOL>
__global__ void __launch_bounds__(256)
gemm_bf16x3(const float* __restrict__ A, const float* __restrict__ Bm,
            float* __restrict__ Cm,
            int Kd, int lda, int ldb, int ldc,
            long long asb, long long ash,
            long long bsb, long long bsh,
            long long csb, long long csh, int HB) {
    constexpr int BM = 128, BN = 128, BK = 32;
    const int z = blockIdx.z;
    const int bb = z / HB, hh = z - bb * HB;
    A  += (size_t)bb * asb + (size_t)hh * ash;
    Bm += (size_t)bb * bsb + (size_t)hh * bsh;
    Cm += (size_t)bb * csb + (size_t)hh * csh;
    const int m0 = blockIdx.y * BM;
    const int n0 = blockIdx.x * BN;

    __shared__ __align__(16) __nv_bfloat16 As_hi[BM][BK + 8];
    __shared__ __align__(16) __nv_bfloat16 As_lo[BM][BK + 8];
    constexpr int BR  = BCOL ? BN : BK;
    constexpr int BCn = BCOL ? (BK + 8) : (BN + 8);
    __shared__ __align__(16) __nv_bfloat16 Bs_hi[BR][BCn];
    __shared__ __align__(16) __nv_bfloat16 Bs_lo[BR][BCn];

    const int tid  = threadIdx.x;
    const int warp = tid >> 5;
    const int wm   = warp & 1;   // 2 warps along M (64 rows each)
    const int wn   = warp >> 1;  // 4 warps along N (32 cols each)

    wmma::fragment<wmma::accumulator, 16, 16, 16, float> acc[4][2];
    #pragma unroll
    for (int i = 0; i < 4; i++)
        #pragma unroll
        for (int j = 0; j < 2; j++) wmma::fill_fragment(acc[i][j], 0.0f);

    for (int k0 = 0; k0 < Kd; k0 += BK) {
        // ---- stage A tile (128x32) as hi/lo bf16 ----
        #pragma unroll
        for (int i = 0; i < 4; i++) {
            int idx = tid + i * 256;
            int r = idx >> 3;
            int c = (idx & 7) * 4;
            float4 v = *reinterpret_cast<const float4*>(
                A + (size_t)(m0 + r) * lda + k0 + c);
            float f[4] = { v.x, v.y, v.z, v.w };
            #pragma unroll
            for (int e = 0; e < 4; e++) {
                __nv_bfloat16 h = __float2bfloat16(f[e]);
                As_hi[r][c + e] = h;
                As_lo[r][c + e] = __float2bfloat16(f[e] - __bfloat162float(h));
            }
        }
        // ---- stage B tile ----
        if constexpr (BCOL) {
            // B stored (N x Kd) row-major; smem layout Bs[n][k]
            #pragma unroll
            for (int i = 0; i < 4; i++) {
                int idx = tid + i * 256;
                int r = idx >> 3;          // n: 0..127
                int c = (idx & 7) * 4;     // k: 0..28
                float4 v = *reinterpret_cast<const float4*>(
                    Bm + (size_t)(n0 + r) * ldb + k0 + c);
                float f[4] = { v.x, v.y, v.z, v.w };
                #pragma unroll
                for (int e = 0; e < 4; e++) {
                    __nv_bfloat16 h = __float2bfloat16(f[e]);
                    Bs_hi[r][c + e] = h;
                    Bs_lo[r][c + e] = __float2bfloat16(f[e] - __bfloat162float(h));
                }
            }
        } else {
            // B stored (Kd x N) row-major; smem layout Bs[k][n]
            #pragma unroll
            for (int i = 0; i < 4; i++) {
                int idx = tid + i * 256;
                int r = idx >> 5;          // k: 0..31
                int c = (idx & 31) * 4;    // n: 0..124
                float4 v = *reinterpret_cast<const float4*>(
                    Bm + (size_t)(k0 + r) * ldb + n0 + c);
                float f[4] = { v.x, v.y, v.z, v.w };
                #pragma unroll
                for (int e = 0; e < 4; e++) {
                    __nv_bfloat16 h = __float2bfloat16(f[e]);
                    Bs_hi[r][c + e] = h;
                    Bs_lo[r][c + e] = __float2bfloat16(f[e] - __bfloat162float(h));
                }
            }
        }
        __syncthreads();

        #pragma unroll
        for (int kk = 0; kk < BK / 16; kk++) {
            wmma::fragment<wmma::matrix_a, 16, 16, 16, __nv_bfloat16, wmma::row_major> ah[4], al[4];
            #pragma unroll
            for (int i = 0; i < 4; i++) {
                wmma::load_matrix_sync(ah[i], &As_hi[wm * 64 + 16 * i][kk * 16], BK + 8);
                wmma::load_matrix_sync(al[i], &As_lo[wm * 64 + 16 * i][kk * 16], BK + 8);
            }
            #pragma unroll
            for (int j = 0; j < 2; j++) {
                if constexpr (BCOL) {
                    wmma::fragment<wmma::matrix_b, 16, 16, 16, __nv_bfloat16, wmma::col_major> bh, bl;
                    wmma::load_matrix_sync(bh, &Bs_hi[wn * 32 + 16 * j][kk * 16], BK + 8);
                    wmma::load_matrix_sync(bl, &Bs_lo[wn * 32 + 16 * j][kk * 16], BK + 8);
                    #pragma unroll
                    for (int i = 0; i < 4; i++) {
                        wmma::mma_sync(acc[i][j], ah[i], bh, acc[i][j]);
                        wmma::mma_sync(acc[i][j], al[i], bh, acc[i][j]);
                        wmma::mma_sync(acc[i][j], ah[i], bl, acc[i][j]);
                    }
                } else {
                    wmma::fragment<wmma::matrix_b, 16, 16, 16, __nv_bfloat16, wmma::row_major> bh, bl;
                    wmma::load_matrix_sync(bh, &Bs_hi[kk * 16][wn * 32 + 16 * j], BN + 8);
                    wmma::load_matrix_sync(bl, &Bs_lo[kk * 16][wn * 32 + 16 * j], BN + 8);
                    #pragma unroll
                    for (int i = 0; i < 4; i++) {
                        wmma::mma_sync(acc[i][j], ah[i], bh, acc[i][j]);
                        wmma::mma_sync(acc[i][j], al[i], bh, acc[i][j]);
                        wmma::mma_sync(acc[i][j], ah[i], bl, acc[i][j]);
                    }
                }
            }
        }
        __syncthreads();
    }

    #pragma unroll
    for (int i = 0; i < 4; i++)
        #pragma unroll
        for (int j = 0; j < 2; j++)
            wmma::store_matrix_sync(
                Cm + (size_t)(m0 + wm * 64 + 16 * i) * ldc + n0 + wn * 32 + 16 * j,
                acc[i][j], ldc, wmma::mem_row_major);
}

// ---------------------------------------------------------------------------
// C[i] += bias[i % N]   (vectorized, grid-stride)
// ---------------------------------------------------------------------------
__global__ void bias_add_kernel(float* __restrict__ C, const float* __restrict__ bias,
                                int N, int total4) {
    int i = blockIdx.x * blockDim.x + threadIdx.x;
    const int stride = gridDim.x * blockDim.x;
    for (; i < total4; i += stride) {
        int col = (i * 4) % N;
        float4 bv = *reinterpret_cast<const float4*>(&bias[col]);
        float4* p = reinterpret_cast<float4*>(C) + i;
        float4 v = *p;
        v.x += bv.x; v.y += bv.y; v.z += bv.z; v.w += bv.w;
        *p = v;
    }
}

// ---------------------------------------------------------------------------
// Masked softmax over K=1024, alpha applied on read. One block per (b,h,l) row.
// ---------------------------------------------------------------------------
__global__ void softmax_kernel(float* __restrict__ sc, const int* __restrict__ k_lens) {
    __shared__ float red[33];
    const int row = blockIdx.x;            // 0 .. B*H*L-1
    const int bidx = row / (Hc * Lc);
    const int klen = k_lens[bidx];
    float* p = sc + (size_t)row * Kc;
    const int t = threadIdx.x;
    const int j0 = t * 4;
    const float alpha = 0.08838834764831845f;  // 1/sqrt(128)

    float4 v = *reinterpret_cast<const float4*>(&p[j0]);
    float vv[4] = { v.x, v.y, v.z, v.w };
    float mx = -1e30f;
    #pragma unroll
    for (int i = 0; i < 4; i++) {
        vv[i] = (j0 + i < klen) ? vv[i] * alpha : -1e30f;
        mx = fmaxf(mx, vv[i]);
    }
    mx = block_max256(mx, red);
    float e[4]; float s = 0.0f;
    #pragma unroll
    for (int i = 0; i < 4; i++) {
        e[i] = (j0 + i < klen) ? expf(vv[i] - mx) : 0.0f;
        s += e[i];
    }
    s = block_sum256(s, red);
    float inv = 1.0f / s;
    float4 o = make_float4(e[0] * inv, e[1] * inv, e[2] * inv, e[3] * inv);
    *reinterpret_cast<float4*>(&p[j0]) = o;
}

// ---------------------------------------------------------------------------
// Zero attention-output rows where l >= q_lens[b]  (qmask before Wo)
// ---------------------------------------------------------------------------
__global__ void qmask_kernel(float* __restrict__ attn, const int* __restrict__ q_lens) {
    const int row = blockIdx.x;      // 0 .. B*L-1
    const int bidx = row / Lc;
    const int l = row - bidx * Lc;
    if (l < q_lens[bidx]) return;
    float* p = attn + (size_t)row * Dc;
    const int t = threadIdx.x;
    float4 z = make_float4(0.f, 0.f, 0.f, 0.f);
    *reinterpret_cast<float4*>(&p[t * 4]) = z;
    *reinterpret_cast<float4*>(&p[t * 4 + 1024]) = z;
}

// ---------------------------------------------------------------------------
// Final epilogue: out = (out + bo) * gate[b],  gate = t_emb[:,2] + ssg[2]
// ---------------------------------------------------------------------------
__global__ void final_epi_kernel(float* __restrict__ out,
                                 const float* __restrict__ bo,
                                 const float* __restrict__ t_emb,
                                 const float* __restrict__ ssg) {
    const int row = blockIdx.x;      // 0 .. B*L-1
    const int bidx = row / Lc;
    const int t = threadIdx.x;
    const float* gt = t_emb + (size_t)(bidx * 3 + 2) * Dc;
    const float* gs = ssg + 2 * Dc;
    float* p = out + (size_t)row * Dc;
    #pragma unroll
    for (int half = 0; half < 2; half++) {
        int c = t * 4 + half * 1024;
        float4 v  = *reinterpret_cast<const float4*>(&p[c]);
        float4 bv = *reinterpret_cast<const float4*>(&bo[c]);
        float4 g1 = *reinterpret_cast<const float4*>(&gt[c]);
        float4 g2 = *reinterpret_cast<const float4*>(&gs[c]);
        float4 o;
        o.x = (v.x + bv.x) * (g1.x + g2.x);
        o.y = (v.y + bv.y) * (g1.y + g2.y);
        o.z = (v.z + bv.z) * (g1.z + g2.z);
        o.w = (v.w + bv.w) * (g1.w + g2.w);
        *reinterpret_cast<float4*>(&p[c]) = o;
    }
}

// ---------------------------------------------------------------------------
// Launch
// ---------------------------------------------------------------------------
extern "C" void kernel_launch(void* const* d_in, const int* in_sizes, int n_in,
                              void* d_out, int out_size) {
    (void)in_sizes; (void)n_in; (void)out_size;
    const float* x       = (const float*)d_in[0];
    const float* latents = (const float*)d_in[1];
    const float* t_emb   = (const float*)d_in[2];
    const int*   q_lens  = (const int*)  d_in[3];
    const int*   k_lens  = (const int*)  d_in[4];
    const float* ln_kv_w = (const float*)d_in[5];
    const float* ln_kv_b = (const float*)d_in[6];
    const float* ssg     = (const float*)d_in[7];
    const float* Wq      = (const float*)d_in[8];
    const float* bq      = (const float*)d_in[9];
    const float* Wkv     = (const float*)d_in[10];
    const float* bkv     = (const float*)d_in[11];
    const float* Wo      = (const float*)d_in[12];
    const float* bo      = (const float*)d_in[13];
    float* out = (float*)d_out;

    float *xk, *lat, *q, *kv, *sc, *at;
    cudaGetSymbolAddress((void**)&xk,  g_xk);
    cudaGetSymbolAddress((void**)&lat, g_lat);
    cudaGetSymbolAddress((void**)&q,   g_q);
    cudaGetSymbolAddress((void**)&kv,  g_kv);
    cudaGetSymbolAddress((void**)&sc,  g_scores);
    cudaGetSymbolAddress((void**)&at,  g_attn);

    // 1) LayerNorms
    ln_x_kernel<<<Bc * Kc, 256>>>(x, ln_kv_w, ln_kv_b, xk);
    ln_lat_kernel<<<Bc * Lc, 256>>>(latents, t_emb, ssg, lat);

    // 2) q = lat @ Wq (+bq)
    gemm_bf16x3<false><<<dim3(Dc / 128, (Bc * Lc) / 128, 1), 256>>>(
        lat, Wq, q, Dc, Dc, Dc, Dc, 0, 0, 0, 0, 0, 0, 1);
    bias_add_kernel<<<2048, 256>>>(q, bq, Dc, (Bc * Lc * Dc) / 4);

    // 3) kv = xk @ Wkv (+bkv)
    gemm_bf16x3<false><<<dim3(2 * Dc / 128, (Bc * Kc) / 128, 1), 256>>>(
        xk, Wkv, kv, KVc, KVc, 2 * Dc, 2 * Dc, 0, 0, 0, 0, 0, 0, 1);
    bias_add_kernel<<<4096, 256>>>(kv, bkv, 2 * Dc, (Bc * Kc * 2 * Dc) / 4);

    // 4) scores[b,h] = q[b,:,h,:] @ k[b,:,h,:]^T   (alpha folded into softmax)
    gemm_bf16x3<true><<<dim3(Kc / 128, Lc / 128, Bc * Hc), 256>>>(
        q, kv, sc, Cc, Dc, 2 * Dc, Kc,
        (long long)Lc * Dc, (long long)Cc,
        (long long)Kc * 2 * Dc, (long long)Cc,
        (long long)Hc * Lc * Kc, (long long)Lc * Kc, Hc);

    // 5) masked softmax
    softmax_kernel<<<Bc * Hc * Lc, 256>>>(sc, k_lens);

    // 6) attn_out[b,:,h,:] = attn[b,h] @ v[b,:,h,:]
    gemm_bf16x3<false><<<dim3(1, Lc / 128, Bc * Hc), 256>>>(
        sc, kv + Dc, at, Kc, Kc, 2 * Dc, Dc,
        (long long)Hc * Lc * Kc, (long long)Lc * Kc,
        (long long)Kc * 2 * Dc, (long long)Cc,
        (long long)Lc * Dc, (long long)Cc, Hc);

    // 7) qmask (no-op for q_lens == L, but correct in general)
    qmask_kernel<<<Bc * Lc, 256>>>(at, q_lens);

    // 8) out = attn_out @ Wo, then (+bo)*gate
    gemm_bf16x3<false><<<dim3(Dc / 128, (Bc * Lc) / 128, 1), 256>>>(
        at, Wo, out, Dc, Dc, Dc, Dc, 0, 0, 0, 0, 0, 0, 1);
    final_epi_kernel<<<Bc * Lc, 256>>>(out, bo, t_emb, ssg);
}

// round 2
// speedup vs baseline: 1.2212x; 1.2212x over previous
#include <cuda_runtime.h>
#include <cuda_bf16.h>
#include <mma.h>
#include <cstdint>

using namespace nvcuda;
typedef __nv_bfloat16 bf16;

// Problem dims
constexpr int Bc  = 4;
constexpr int Lc  = 512;
constexpr int Dc  = 2048;
constexpr int Hc  = 16;
constexpr int Cc  = 128;
constexpr int KVc = 2048;
constexpr int Kc  = 1024;   // T*LA

// ---------------------------------------------------------------------------
// Scratch (device globals — allocation-free rule)
// ---------------------------------------------------------------------------
__device__ bf16  g_xk_hi[(size_t)Bc * Kc * KVc];
__device__ bf16  g_xk_lo[(size_t)Bc * Kc * KVc];
__device__ bf16  g_lat_hi[(size_t)Bc * Lc * Dc];
__device__ bf16  g_lat_lo[(size_t)Bc * Lc * Dc];
__device__ bf16  g_q_hi[(size_t)Bc * Lc * Dc];
__device__ bf16  g_q_lo[(size_t)Bc * Lc * Dc];
__device__ bf16  g_kv_hi[(size_t)Bc * Kc * 2 * Dc];
__device__ bf16  g_kv_lo[(size_t)Bc * Kc * 2 * Dc];
__device__ float g_scores[(size_t)Bc * Hc * Lc * Kc];
__device__ bf16  g_p_hi[(size_t)Bc * Hc * Lc * Kc];
__device__ bf16  g_p_lo[(size_t)Bc * Hc * Lc * Kc];
__device__ bf16  g_at_hi[(size_t)Bc * Lc * Dc];
__device__ bf16  g_at_lo[(size_t)Bc * Lc * Dc];
__device__ bf16  g_wq_hi[(size_t)Dc * Dc];
__device__ bf16  g_wq_lo[(size_t)Dc * Dc];
__device__ bf16  g_wkv_hi[(size_t)KVc * 2 * Dc];
__device__ bf16  g_wkv_lo[(size_t)KVc * 2 * Dc];
__device__ bf16  g_wo_hi[(size_t)Dc * Dc];
__device__ bf16  g_wo_lo[(size_t)Dc * Dc];

// ---------------------------------------------------------------------------
// Small helpers
// ---------------------------------------------------------------------------
__device__ __forceinline__ void cp_async16(void* smem_dst, const void* gmem_src) {
    unsigned s = (unsigned)__cvta_generic_to_shared(smem_dst);
    asm volatile("cp.async.cg.shared.global [%0], [%1], 16;\n" :: "r"(s), "l"(gmem_src));
}
__device__ __forceinline__ void cp_commit() { asm volatile("cp.async.commit_group;\n"); }
__device__ __forceinline__ void cp_wait0()  { asm volatile("cp.async.wait_group 0;\n"); }

struct __align__(8) bf4 { bf16 v[4]; };

__device__ __forceinline__ void split_store4(bf16* hi, bf16* lo, size_t off, float4 f) {
    bf4 H, L;
    float ff[4] = { f.x, f.y, f.z, f.w };
    #pragma unroll
    for (int e = 0; e < 4; e++) {
        bf16 h = __float2bfloat16(ff[e]);
        H.v[e] = h;
        L.v[e] = __float2bfloat16(ff[e] - __bfloat162float(h));
    }
    *reinterpret_cast<bf4*>(hi + off) = H;
    *reinterpret_cast<bf4*>(lo + off) = L;
}

__device__ __forceinline__ float warp_sum(float v) {
    #pragma unroll
    for (int o = 16; o > 0; o >>= 1) v += __shfl_xor_sync(0xffffffffu, v, o);
    return v;
}
__device__ __forceinline__ float warp_max(float v) {
    #pragma unroll
    for (int o = 16; o > 0; o >>= 1) v = fmaxf(v, __shfl_xor_sync(0xffffffffu, v, o));
    return v;
}
__device__ __forceinline__ float block_sum256(float v, float* red) {
    int lane = threadIdx.x & 31, w = threadIdx.x >> 5;
    v = warp_sum(v);
    if (lane == 0) red[w] = v;
    __syncthreads();
    if (w == 0) {
        float t = (lane < 8) ? red[lane] : 0.0f;
        t = warp_sum(t);
        if (lane == 0) red[32] = t;
    }
    __syncthreads();
    float r = red[32];
    __syncthreads();
    return r;
}
__device__ __forceinline__ float block_max256(float v, float* red) {
    int lane = threadIdx.x & 31, w = threadIdx.x >> 5;
    v = warp_max(v);
    if (lane == 0) red[w] = v;
    __syncthreads();
    if (w == 0) {
        float t = (lane < 8) ? red[lane] : -1e30f;
        t = warp_max(t);
        if (lane == 0) red[32] = t;
    }
    __syncthreads();
    float r = red[32];
    __syncthreads();
    return r;
}

// ---------------------------------------------------------------------------
// fp32 -> bf16 hi/lo splitter (weights), grid-stride over float4s
// ---------------------------------------------------------------------------
__global__ void split_kernel(const float* __restrict__ W,
                             bf16* __restrict__ hi, bf16* __restrict__ lo,
                             int total4) {
    int i = blockIdx.x * blockDim.x + threadIdx.x;
    const int stride = gridDim.x * blockDim.x;
    for (; i < total4; i += stride) {
        float4 v = reinterpret_cast<const float4*>(W)[i];
        split_store4(hi, lo, (size_t)i * 4, v);
    }
}

// ---------------------------------------------------------------------------
// LayerNorm of x -> xk hi/lo  (rows = B*K, width = KV = 2048)
// ---------------------------------------------------------------------------
__global__ void ln_x_kernel(const float* __restrict__ x,
                            const float* __restrict__ w,
                            const float* __restrict__ b,
                            bf16* __restrict__ out_hi, bf16* __restrict__ out_lo) {
    __shared__ float red[33];
    const int row = blockIdx.x;
    const size_t base = (size_t)row * KVc;
    const int t = threadIdx.x;
    const int c0 = t * 4;
    const int c1 = c0 + 1024;

    float4 v0 = *reinterpret_cast<const float4*>(&x[base + c0]);
    float4 v1 = *reinterpret_cast<const float4*>(&x[base + c1]);

    float s = v0.x + v0.y + v0.z + v0.w + v1.x + v1.y + v1.z + v1.w;
    float mean = block_sum256(s, red) * (1.0f / KVc);

    float d0x = v0.x - mean, d0y = v0.y - mean, d0z = v0.z - mean, d0w = v0.w - mean;
    float d1x = v1.x - mean, d1y = v1.y - mean, d1z = v1.z - mean, d1w = v1.w - mean;
    float sq = d0x*d0x + d0y*d0y + d0z*d0z + d0w*d0w + d1x*d1x + d1y*d1y + d1z*d1z + d1w*d1w;
    float var = block_sum256(sq, red) * (1.0f / KVc);
    float rstd = rsqrtf(var + 1e-5f);

    float4 w0 = *reinterpret_cast<const float4*>(&w[c0]);
    float4 w1 = *reinterpret_cast<const float4*>(&w[c1]);
    float4 b0 = *reinterpret_cast<const float4*>(&b[c0]);
    float4 b1 = *reinterpret_cast<const float4*>(&b[c1]);

    float4 o0 = make_float4(d0x*rstd*w0.x + b0.x, d0y*rstd*w0.y + b0.y,
                            d0z*rstd*w0.z + b0.z, d0w*rstd*w0.w + b0.w);
    float4 o1 = make_float4(d1x*rstd*w1.x + b1.x, d1y*rstd*w1.y + b1.y,
                            d1z*rstd*w1.z + b1.z, d1w*rstd*w1.w + b1.w);
    split_store4(out_hi, out_lo, base + c0, o0);
    split_store4(out_hi, out_lo, base + c1, o1);
}

// ---------------------------------------------------------------------------
// LayerNorm of latents + adaLN modulation -> lat hi/lo
// ---------------------------------------------------------------------------
__global__ void ln_lat_kernel(const float* __restrict__ latents,
                              const float* __restrict__ t_emb,
                              const float* __restrict__ ssg,
                              bf16* __restrict__ out_hi, bf16* __restrict__ out_lo) {
    __shared__ float red[33];
    const int row = blockIdx.x;
    const int bidx = row / Lc;
    const size_t base = (size_t)row * Dc;
    const int t = threadIdx.x;
    const int c0 = t * 4;
    const int c1 = c0 + 1024;

    float4 v0 = *reinterpret_cast<const float4*>(&latents[base + c0]);
    float4 v1 = *reinterpret_cast<const float4*>(&latents[base + c1]);

    float s = v0.x + v0.y + v0.z + v0.w + v1.x + v1.y + v1.z + v1.w;
    float mean = block_sum256(s, red) * (1.0f / Dc);

    float d0x = v0.x - mean, d0y = v0.y - mean, d0z = v0.z - mean, d0w = v0.w - mean;
    float d1x = v1.x - mean, d1y = v1.y - mean, d1z = v1.z - mean, d1w = v1.w - mean;
    float sq = d0x*d0x + d0y*d0y + d0z*d0z + d0w*d0w + d1x*d1x + d1y*d1y + d1z*d1z + d1w*d1w;
    float var = block_sum256(sq, red) * (1.0f / Dc);
    float rstd = rsqrtf(var + 1e-5f);

    const float* sh_t = t_emb + (size_t)(bidx * 3 + 0) * Dc;
    const float* sc_t = t_emb + (size_t)(bidx * 3 + 1) * Dc;

    #pragma unroll
    for (int half = 0; half < 2; half++) {
        int c = (half == 0) ? c0 : c1;
        float dv[4] = { (half ? d1x : d0x), (half ? d1y : d0y),
                        (half ? d1z : d0z), (half ? d1w : d0w) };
        float4 sht = *reinterpret_cast<const float4*>(&sh_t[c]);
        float4 sct = *reinterpret_cast<const float4*>(&sc_t[c]);
        float4 shs = *reinterpret_cast<const float4*>(&ssg[c]);
        float4 scs = *reinterpret_cast<const float4*>(&ssg[Dc + c]);
        float4 o;
        o.x = dv[0]*rstd * (1.0f + sct.x + scs.x) + sht.x + shs.x;
        o.y = dv[1]*rstd * (1.0f + sct.y + scs.y) + sht.y + shs.y;
        o.z = dv[2]*rstd * (1.0f + sct.z + scs.z) + sht.z + shs.z;
        o.w = dv[3]*rstd * (1.0f + sct.w + scs.w) + sht.w + shs.w;
        split_store4(out_hi, out_lo, base + c, o);
    }
}

// ---------------------------------------------------------------------------
// bf16x3 GEMM, operands pre-split, cp.async double-buffered.
//   BCOL=false: C = A @ B      (B row-major Kd x N)
//   BCOL=true : C = A @ B^T    (B row-major N x Kd)
// OMODE: 0 = fp32 C store (scores)
//        1 = bf16 hi/lo store (+ optional bias)
//        2 = fp32 store with (acc + bias) * gate (final proj)
// Tile 128x128xBK32, 256 threads, 8 warps (2x4), warp = 64x32 out.
// ---------------------------------------------------------------------------
constexpr int SM_APITCH = 40;    // bf16 pitch for A / BCOL-B tiles
constexpr int SM_BPITCH = 136;   // bf16 pitch for row-major B tiles
constexpr int SM_SLOT   = 10240; // bytes per array slot
constexpr int SM_STAGE  = 4 * SM_SLOT;
constexpr int SM_TOTAL  = 2 * SM_STAGE;  // 81920

template <bool BCOL, int OMODE>
__global__ void __launch_bounds__(256)
gemm_ks(const bf16* __restrict__ Ah, const bf16* __restrict__ Al,
        const bf16* __restrict__ Bh, const bf16* __restrict__ Bl,
        float* __restrict__ C, bf16* __restrict__ Ch, bf16* __restrict__ Cl,
        const float* __restrict__ bias,
        const float* __restrict__ t_emb, const float* __restrict__ ssg,
        int Kd, int lda, int ldb, int ldc,
        long long asb, long long ash,
        long long bsb, long long bsh,
        long long csb, long long csh, int HB) {
    extern __shared__ char sm[];
    const int z = blockIdx.z;
    const int bb = z / HB, hh = z - bb * HB;
    Ah += (size_t)bb * asb + (size_t)hh * ash;
    Al += (size_t)bb * asb + (size_t)hh * ash;
    Bh += (size_t)bb * bsb + (size_t)hh * bsh;
    Bl += (size_t)bb * bsb + (size_t)hh * bsh;
    const long long coff = (long long)bb * csb + (long long)hh * csh;
    if (OMODE == 0) C += coff; else if (OMODE == 1) { Ch += coff; Cl += coff; }

    const int m0 = blockIdx.y * 128;
    const int n0 = blockIdx.x * 128;
    const int tid  = threadIdx.x;
    const int warp = tid >> 5;
    const int lane = tid & 31;
    const int wm   = warp & 1;
    const int wn   = warp >> 1;

    wmma::fragment<wmma::accumulator, 16, 16, 16, float> acc[4][2];
    #pragma unroll
    for (int i = 0; i < 4; i++)
        #pragma unroll
        for (int j = 0; j < 2; j++) wmma::fill_fragment(acc[i][j], 0.0f);

    auto load_stage = [&](int st, int k0) {
        char* base = sm + st * SM_STAGE;
        bf16* dAh = (bf16*)(base);
        bf16* dAl = (bf16*)(base + SM_SLOT);
        bf16* dBh = (bf16*)(base + 2 * SM_SLOT);
        bf16* dBl = (bf16*)(base + 3 * SM_SLOT);
        #pragma unroll
        for (int i = 0; i < 2; i++) {
            int idx = tid + i * 256;
            int r = idx >> 2;
            int c = (idx & 3) * 8;
            size_t g = (size_t)(m0 + r) * lda + k0 + c;
            cp_async16(dAh + r * SM_APITCH + c, Ah + g);
            cp_async16(dAl + r * SM_APITCH + c, Al + g);
        }
        if constexpr (BCOL) {
            #pragma unroll
            for (int i = 0; i < 2; i++) {
                int idx = tid + i * 256;
                int r = idx >> 2;
                int c = (idx & 3) * 8;
                size_t g = (size_t)(n0 + r) * ldb + k0 + c;
                cp_async16(dBh + r * SM_APITCH + c, Bh + g);
                cp_async16(dBl + r * SM_APITCH + c, Bl + g);
            }
        } else {
            #pragma unroll
            for (int i = 0; i < 2; i++) {
                int idx = tid + i * 256;
                int r = idx >> 4;
                int c = (idx & 15) * 8;
                size_t g = (size_t)(k0 + r) * ldb + n0 + c;
                cp_async16(dBh + r * SM_BPITCH + c, Bh + g);
                cp_async16(dBl + r * SM_BPITCH + c, Bl + g);
            }
        }
    };

    const int nIter = Kd >> 5;
    load_stage(0, 0);
    cp_commit();

    for (int it = 0; it < nIter; ++it) {
        cp_wait0();
        __syncthreads();
        if (it + 1 < nIter) {
            load_stage((it + 1) & 1, (it + 1) << 5);
            cp_commit();
        }
        // compute stage it&1
        char* base = sm + (it & 1) * SM_STAGE;
        const bf16* sAh = (const bf16*)(base);
        const bf16* sAl = (const bf16*)(base + SM_SLOT);
        const bf16* sBh = (const bf16*)(base + 2 * SM_SLOT);
        const bf16* sBl = (const bf16*)(base + 3 * SM_SLOT);
        #pragma unroll
        for (int kk = 0; kk < 2; kk++) {
            wmma::fragment<wmma::matrix_a, 16, 16, 16, bf16, wmma::row_major> ah[4], al[4];
            #pragma unroll
            for (int i = 0; i < 4; i++) {
                wmma::load_matrix_sync(ah[i], sAh + (wm * 64 + 16 * i) * SM_APITCH + kk * 16, SM_APITCH);
                wmma::load_matrix_sync(al[i], sAl + (wm * 64 + 16 * i) * SM_APITCH + kk * 16, SM_APITCH);
            }
            #pragma unroll
            for (int j = 0; j < 2; j++) {
                if constexpr (BCOL) {
                    wmma::fragment<wmma::matrix_b, 16, 16, 16, bf16, wmma::col_major> bh, bl;
                    wmma::load_matrix_sync(bh, sBh + (wn * 32 + 16 * j) * SM_APITCH + kk * 16, SM_APITCH);
                    wmma::load_matrix_sync(bl, sBl + (wn * 32 + 16 * j) * SM_APITCH + kk * 16, SM_APITCH);
                    #pragma unroll
                    for (int i = 0; i < 4; i++) {
                        wmma::mma_sync(acc[i][j], ah[i], bh, acc[i][j]);
                        wmma::mma_sync(acc[i][j], al[i], bh, acc[i][j]);
                        wmma::mma_sync(acc[i][j], ah[i], bl, acc[i][j]);
                    }
                } else {
                    wmma::fragment<wmma::matrix_b, 16, 16, 16, bf16, wmma::row_major> bh, bl;
                    wmma::load_matrix_sync(bh, sBh + (kk * 16) * SM_BPITCH + wn * 32 + 16 * j, SM_BPITCH);
                    wmma::load_matrix_sync(bl, sBl + (kk * 16) * SM_BPITCH + wn * 32 + 16 * j, SM_BPITCH);
                    #pragma unroll
                    for (int i = 0; i < 4; i++) {
                        wmma::mma_sync(acc[i][j], ah[i], bh, acc[i][j]);
                        wmma::mma_sync(acc[i][j], al[i], bh, acc[i][j]);
                        wmma::mma_sync(acc[i][j], ah[i], bl, acc[i][j]);
                    }
                }
            }
        }
        __syncthreads();
    }

    if constexpr (OMODE == 0) {
        #pragma unroll
        for (int i = 0; i < 4; i++)
            #pragma unroll
            for (int j = 0; j < 2; j++)
                wmma::store_matrix_sync(
                    C + (size_t)(m0 + wm * 64 + 16 * i) * ldc + n0 + wn * 32 + 16 * j,
                    acc[i][j], ldc, wmma::mem_row_major);
    } else {
        // stage accumulators to smem, then convert/epilogue
        float* stag = (float*)(sm) + warp * 2560;  // 64 x 40 floats per warp
        #pragma unroll
        for (int i = 0; i < 4; i++)
            #pragma unroll
            for (int j = 0; j < 2; j++)
                wmma::store_matrix_sync(stag + (16 * i) * 40 + 16 * j, acc[i][j], 40,
                                        wmma::mem_row_major);
        __syncwarp();
        const int bidx = m0 / Lc;  // tiles never straddle a batch (Lc % 128 == 0)
        #pragma unroll
        for (int itr = 0; itr < 16; itr++) {
            int g = lane + itr * 32;
            int r = g >> 3;
            int c = (g & 7) * 4;
            float4 v = *reinterpret_cast<const float4*>(stag + r * 40 + c);
            int gr = m0 + wm * 64 + r;
            int gc = n0 + wn * 32 + c;
            if constexpr (OMODE == 1) {
                if (bias) {
                    float4 bv = *reinterpret_cast<const float4*>(&bias[gc]);
                    v.x += bv.x; v.y += bv.y; v.z += bv.z; v.w += bv.w;
                }
                split_store4(Ch, Cl, (size_t)gr * ldc + gc, v);
            } else {  // OMODE == 2: (v + bias) * gate
                float4 bv = *reinterpret_cast<const float4*>(&bias[gc]);
                float4 g1 = *reinterpret_cast<const float4*>(&t_emb[(size_t)(bidx * 3 + 2) * Dc + gc]);
                float4 g2 = *reinterpret_cast<const float4*>(&ssg[2 * Dc + gc]);
                float4 o;
                o.x = (v.x + bv.x) * (g1.x + g2.x);
                o.y = (v.y + bv.y) * (g1.y + g2.y);
                o.z = (v.z + bv.z) * (g1.z + g2.z);
                o.w = (v.w + bv.w) * (g1.w + g2.w);
                *reinterpret_cast<float4*>(&C[(size_t)gr * ldc + gc]) = o;
            }
        }
    }
}

// ---------------------------------------------------------------------------
// Masked softmax over K=1024; alpha on read; writes bf16 hi/lo probabilities.
// ---------------------------------------------------------------------------
__global__ void softmax_kernel(const float* __restrict__ sc,
                               const int* __restrict__ k_lens,
                               bf16* __restrict__ ph, bf16* __restrict__ pl) {
    __shared__ float red[33];
    const int row = blockIdx.x;            // 0 .. B*H*L-1
    const int bidx = row / (Hc * Lc);
    const int klen = k_lens[bidx];
    const float* p = sc + (size_t)row * Kc;
    const int t = threadIdx.x;
    const int j0 = t * 4;
    const float alpha = 0.08838834764831845f;  // 1/sqrt(128)

    float4 v = *reinterpret_cast<const float4*>(&p[j0]);
    float vv[4] = { v.x, v.y, v.z, v.w };
    float mx = -1e30f;
    #pragma unroll
    for (int i = 0; i < 4; i++) {
        vv[i] = (j0 + i < klen) ? vv[i] * alpha : -1e30f;
        mx = fmaxf(mx, vv[i]);
    }
    mx = block_max256(mx, red);
    float e[4]; float s = 0.0f;
    #pragma unroll
    for (int i = 0; i < 4; i++) {
        e[i] = (j0 + i < klen) ? expf(vv[i] - mx) : 0.0f;
        s += e[i];
    }
    s = block_sum256(s, red);
    float inv = 1.0f / s;
    split_store4(ph, pl, (size_t)row * Kc + j0,
                 make_float4(e[0] * inv, e[1] * inv, e[2] * inv, e[3] * inv));
}

// ---------------------------------------------------------------------------
// Zero attention-output rows where l >= q_lens[b] (hi/lo arrays)
// ---------------------------------------------------------------------------
__global__ void qmask_kernel(bf16* __restrict__ ah, bf16* __restrict__ al,
                             const int* __restrict__ q_lens) {
    const int row = blockIdx.x;      // 0 .. B*L-1
    const int bidx = row / Lc;
    const int l = row - bidx * Lc;
    if (l < q_lens[bidx]) return;
    const int t = threadIdx.x;
    float4 z = make_float4(0.f, 0.f, 0.f, 0.f);
    // D=2048 bf16 = 4096B per array; 256 threads x 16B = 4096B
    *reinterpret_cast<float4*>(&ah[(size_t)row * Dc + t * 8]) = z;
    *reinterpret_cast<float4*>(&al[(size_t)row * Dc + t * 8]) = z;
}

// ---------------------------------------------------------------------------
// Launch
// ---------------------------------------------------------------------------
extern "C" void kernel_launch(void* const* d_in, const int* in_sizes, int n_in,
                              void* d_out, int out_size) {
    (void)in_sizes; (void)n_in; (void)out_size;
    const float* x       = (const float*)d_in[0];
    const float* latents = (const float*)d_in[1];
    const float* t_emb   = (const float*)d_in[2];
    const int*   q_lens  = (const int*)  d_in[3];
    const int*   k_lens  = (const int*)  d_in[4];
    const float* ln_kv_w = (const float*)d_in[5];
    const float* ln_kv_b = (const float*)d_in[6];
    const float* ssg     = (const float*)d_in[7];
    const float* Wq      = (const float*)d_in[8];
    const float* bq      = (const float*)d_in[9];
    const float* Wkv     = (const float*)d_in[10];
    const float* bkv     = (const float*)d_in[11];
    const float* Wo      = (const float*)d_in[12];
    const float* bo      = (const float*)d_in[13];
    float* out = (float*)d_out;

    bf16 *xk_h, *xk_l, *lat_h, *lat_l, *q_h, *q_l, *kv_h, *kv_l;
    bf16 *p_h, *p_l, *at_h, *at_l, *wq_h, *wq_l, *wkv_h, *wkv_l, *wo_h, *wo_l;
    float* sc;
    cudaGetSymbolAddress((void**)&xk_h, g_xk_hi);   cudaGetSymbolAddress((void**)&xk_l, g_xk_lo);
    cudaGetSymbolAddress((void**)&lat_h, g_lat_hi); cudaGetSymbolAddress((void**)&lat_l, g_lat_lo);
    cudaGetSymbolAddress((void**)&q_h, g_q_hi);     cudaGetSymbolAddress((void**)&q_l, g_q_lo);
    cudaGetSymbolAddress((void**)&kv_h, g_kv_hi);   cudaGetSymbolAddress((void**)&kv_l, g_kv_lo);
    cudaGetSymbolAddress((void**)&p_h, g_p_hi);     cudaGetSymbolAddress((void**)&p_l, g_p_lo);
    cudaGetSymbolAddress((void**)&at_h, g_at_hi);   cudaGetSymbolAddress((void**)&at_l, g_at_lo);
    cudaGetSymbolAddress((void**)&wq_h, g_wq_hi);   cudaGetSymbolAddress((void**)&wq_l, g_wq_lo);
    cudaGetSymbolAddress((void**)&wkv_h, g_wkv_hi); cudaGetSymbolAddress((void**)&wkv_l, g_wkv_lo);
    cudaGetSymbolAddress((void**)&wo_h, g_wo_hi);   cudaGetSymbolAddress((void**)&wo_l, g_wo_lo);
    cudaGetSymbolAddress((void**)&sc, g_scores);

    cudaFuncSetAttribute(gemm_ks<false, 1>, cudaFuncAttributeMaxDynamicSharedMemorySize, SM_TOTAL);
    cudaFuncSetAttribute(gemm_ks<true, 0>,  cudaFuncAttributeMaxDynamicSharedMemorySize, SM_TOTAL);
    cudaFuncSetAttribute(gemm_ks<false, 2>, cudaFuncAttributeMaxDynamicSharedMemorySize, SM_TOTAL);

    // 0) split weights to bf16 hi/lo
    split_kernel<<<2048, 256>>>(Wq,  wq_h,  wq_l,  Dc * Dc / 4);
    split_kernel<<<2048, 256>>>(Wkv, wkv_h, wkv_l, KVc * 2 * Dc / 4);
    split_kernel<<<2048, 256>>>(Wo,  wo_h,  wo_l,  Dc * Dc / 4);

    // 1) LayerNorms (emit bf16 hi/lo)
    ln_x_kernel<<<Bc * Kc, 256>>>(x, ln_kv_w, ln_kv_b, xk_h, xk_l);
    ln_lat_kernel<<<Bc * Lc, 256>>>(latents, t_emb, ssg, lat_h, lat_l);

    // 2) q = lat @ Wq + bq  -> bf16 hi/lo
    gemm_ks<false, 1><<<dim3(Dc / 128, (Bc * Lc) / 128, 1), 256, SM_TOTAL>>>(
        lat_h, lat_l, wq_h, wq_l, nullptr, q_h, q_l, bq, nullptr, nullptr,
        Dc, Dc, Dc, Dc, 0, 0, 0, 0, 0, 0, 1);

    // 3) kv = xk @ Wkv + bkv -> bf16 hi/lo
    gemm_ks<false, 1><<<dim3(2 * Dc / 128, (Bc * Kc) / 128, 1), 256, SM_TOTAL>>>(
        xk_h, xk_l, wkv_h, wkv_l, nullptr, kv_h, kv_l, bkv, nullptr, nullptr,
        KVc, KVc, 2 * Dc, 2 * Dc, 0, 0, 0, 0, 0, 0, 1);

    // 4) scores[b,h] = q[b,:,h,:] @ k[b,:,h,:]^T  (fp32; alpha in softmax)
    gemm_ks<true, 0><<<dim3(Kc / 128, Lc / 128, Bc * Hc), 256, SM_TOTAL>>>(
        q_h, q_l, kv_h, kv_l, sc, nullptr, nullptr, nullptr, nullptr, nullptr,
        Cc, Dc, 2 * Dc, Kc,
        (long long)Lc * Dc, (long long)Cc,
        (long long)Kc * 2 * Dc, (long long)Cc,
        (long long)Hc * Lc * Kc, (long long)Lc * Kc, Hc);

    // 5) masked softmax -> p hi/lo
    softmax_kernel<<<Bc * Hc * Lc, 256>>>(sc, k_lens, p_h, p_l);

    // 6) attn_out[b,:,h,:] = p[b,h] @ v[b,:,h,:] -> bf16 hi/lo
    gemm_ks<false, 1><<<dim3(1, Lc / 128, Bc * Hc), 256, SM_TOTAL>>>(
        p_h, p_l, kv_h + Dc, kv_l + Dc, nullptr, at_h, at_l, nullptr, nullptr, nullptr,
        Kc, Kc, 2 * Dc, Dc,
        (long long)Hc * Lc * Kc, (long long)Lc * Kc,
        (long long)Kc * 2 * Dc, (long long)Cc,
        (long long)Lc * Dc, (long long)Cc, Hc);

    // 7) qmask (general-correct; no-op when q_lens == L)
    qmask_kernel<<<Bc * Lc, 256>>>(at_h, at_l, q_lens);

    // 8) out = (at @ Wo + bo) * gate
    gemm_ks<false, 2><<<dim3(Dc / 128, (Bc * Lc) / 128, 1), 256, SM_TOTAL>>>(
        at_h, at_l, wo_h, wo_l, out, nullptr, nullptr, bo, t_emb, ssg,
        Dc, Dc, Dc, Dc, 0, 0, 0, 0, 0, 0, 1);
}

// round 4
// speedup vs baseline: 1.3205x; 1.0813x over previous
#include <cuda_runtime.h>
#include <cuda_bf16.h>
#include <mma.h>
#include <cstdint>

using namespace nvcuda;
typedef __nv_bfloat16 bf16;

// Problem dims
constexpr int Bc  = 4;
constexpr int Lc  = 512;
constexpr int Dc  = 2048;
constexpr int Hc  = 16;
constexpr int Cc  = 128;
constexpr int KVc = 2048;
constexpr int Kc  = 1024;   // T*LA

// ---------------------------------------------------------------------------
// Scratch (device globals — allocation-free rule)
// ---------------------------------------------------------------------------
__device__ bf16  g_xk_hi[(size_t)Bc * Kc * KVc];
__device__ bf16  g_xk_lo[(size_t)Bc * Kc * KVc];
__device__ bf16  g_lat_hi[(size_t)Bc * Lc * Dc];
__device__ bf16  g_lat_lo[(size_t)Bc * Lc * Dc];
__device__ bf16  g_q_hi[(size_t)Bc * Lc * Dc];
__device__ bf16  g_q_lo[(size_t)Bc * Lc * Dc];
__device__ bf16  g_kv_hi[(size_t)Bc * Kc * 2 * Dc];
__device__ bf16  g_kv_lo[(size_t)Bc * Kc * 2 * Dc];
__device__ float g_scores[(size_t)Bc * Hc * Lc * Kc];
__device__ bf16  g_p_hi[(size_t)Bc * Hc * Lc * Kc];
__device__ bf16  g_p_lo[(size_t)Bc * Hc * Lc * Kc];
__device__ bf16  g_at_hi[(size_t)Bc * Lc * Dc];
__device__ bf16  g_at_lo[(size_t)Bc * Lc * Dc];
__device__ bf16  g_wq_hi[(size_t)Dc * Dc];
__device__ bf16  g_wq_lo[(size_t)Dc * Dc];
__device__ bf16  g_wkv_hi[(size_t)KVc * 2 * Dc];
__device__ bf16  g_wkv_lo[(size_t)KVc * 2 * Dc];
__device__ bf16  g_wo_hi[(size_t)Dc * Dc];
__device__ bf16  g_wo_lo[(size_t)Dc * Dc];

// ---------------------------------------------------------------------------
// Helpers
// ---------------------------------------------------------------------------
__device__ __forceinline__ void cp_async16(void* smem_dst, const void* gmem_src) {
    unsigned s = (unsigned)__cvta_generic_to_shared(smem_dst);
    asm volatile("cp.async.cg.shared.global [%0], [%1], 16;\n" :: "r"(s), "l"(gmem_src));
}
__device__ __forceinline__ void cp_commit() { asm volatile("cp.async.commit_group;\n"); }
__device__ __forceinline__ void cp_wait0()  { asm volatile("cp.async.wait_group 0;\n"); }
__device__ __forceinline__ void cp_wait1()  { asm volatile("cp.async.wait_group 1;\n"); }

struct __align__(8) bf4 { bf16 v[4]; };
__device__ __forceinline__ void split_store4(bf16* hi, bf16* lo, size_t off, float4 f) {
    bf4 H, L;
    float ff[4] = { f.x, f.y, f.z, f.w };
    #pragma unroll
    for (int e = 0; e < 4; e++) {
        bf16 h = __float2bfloat16(ff[e]);
        H.v[e] = h;
        L.v[e] = __float2bfloat16(ff[e] - __bfloat162float(h));
    }
    *reinterpret_cast<bf4*>(hi + off) = H;
    *reinterpret_cast<bf4*>(lo + off) = L;
}

__device__ __forceinline__ float warp_sum(float v) {
    #pragma unroll
    for (int o = 16; o > 0; o >>= 1) v += __shfl_xor_sync(0xffffffffu, v, o);
    return v;
}
__device__ __forceinline__ float warp_max(float v) {
    #pragma unroll
    for (int o = 16; o > 0; o >>= 1) v = fmaxf(v, __shfl_xor_sync(0xffffffffu, v, o));
    return v;
}
__device__ __forceinline__ float block_sum256(float v, float* red) {
    int lane = threadIdx.x & 31, w = threadIdx.x >> 5;
    v = warp_sum(v);
    if (lane == 0) red[w] = v;
    __syncthreads();
    if (w == 0) {
        float t = (lane < 8) ? red[lane] : 0.0f;
        t = warp_sum(t);
        if (lane == 0) red[32] = t;
    }
    __syncthreads();
    float r = red[32];
    __syncthreads();
    return r;
}
__device__ __forceinline__ float block_max256(float v, float* red) {
    int lane = threadIdx.x & 31, w = threadIdx.x >> 5;
    v = warp_max(v);
    if (lane == 0) red[w] = v;
    __syncthreads();
    if (w == 0) {
        float t = (lane < 8) ? red[lane] : -1e30f;
        t = warp_max(t);
        if (lane == 0) red[32] = t;
    }
    __syncthreads();
    float r = red[32];
    __syncthreads();
    return r;
}

// ---------------------------------------------------------------------------
// fp32 -> bf16 hi/lo splitter (weights)
// ---------------------------------------------------------------------------
__global__ void split_kernel(const float* __restrict__ W,
                             bf16* __restrict__ hi, bf16* __restrict__ lo,
                             int total4) {
    int i = blockIdx.x * blockDim.x + threadIdx.x;
    const int stride = gridDim.x * blockDim.x;
    for (; i < total4; i += stride) {
        float4 v = reinterpret_cast<const float4*>(W)[i];
        split_store4(hi, lo, (size_t)i * 4, v);
    }
}

// ---------------------------------------------------------------------------
// bf16x3 GEMM, pre-split operands, 3-stage cp.async, wmma m16n16k16.
//   BCOL=false: C = A @ B       (B row-major Kd x N)
//   BCOL=true : C = A @ B^T     (B row-major N x Kd)
// BN: CTA N-tile (128 or 256). CTA M-tile 128, K-chunk 32, 256 threads.
// 8 warps (2 x 4): warp tile 64 x (BN/4).
// OMODE: 0 fp32 store; 1 bf16 hi/lo (+bias); 2 (acc+bias)*gate fp32.
// kmode: 0 none; 1 skip CTA if n0 >= k_lens[b]; 2 shorten K to k_lens[b].
// ---------------------------------------------------------------------------
template <bool BCOL, int BN, int OMODE>
__global__ void __launch_bounds__(256)
gemm_ks(const bf16* __restrict__ Ah, const bf16* __restrict__ Al,
        const bf16* __restrict__ Bh, const bf16* __restrict__ Bl,
        float* __restrict__ C, bf16* __restrict__ Ch, bf16* __restrict__ Cl,
        const float* __restrict__ bias,
        const float* __restrict__ t_emb, const float* __restrict__ ssg,
        const int* __restrict__ klens, int kmode,
        int Kd, int lda, int ldb, int ldc,
        long long asb, long long ash,
        long long bsb, long long bsh,
        long long csb, long long csh, int HB) {
    extern __shared__ char sm[];
    constexpr int APITCH = 40;
    constexpr int BPITCH = BCOL ? 40 : (BN + 8);
    constexpr int ABYTES = 128 * APITCH * 2;                 // per slice
    constexpr int BBYTES = BCOL ? BN * 40 * 2 : 32 * (BN + 8) * 2;
    constexpr int STAGE  = 2 * ABYTES + 2 * BBYTES;
    constexpr int WN     = BN / 64;      // wmma j-tiles per warp (16 cols each)

    const int z  = blockIdx.z;
    const int bb = z / HB, hh = z - bb * HB;
    const int n0 = blockIdx.x * BN;
    const int m0 = blockIdx.y * 128;

    if (kmode == 1 && klens && n0 >= klens[bb]) return;  // fully masked tile

    Ah += (size_t)bb * asb + (size_t)hh * ash;
    Al += (size_t)bb * asb + (size_t)hh * ash;
    Bh += (size_t)bb * bsb + (size_t)hh * bsh;
    Bl += (size_t)bb * bsb + (size_t)hh * bsh;
    const long long coff = (long long)bb * csb + (long long)hh * csh;
    if (OMODE == 0 || OMODE == 2) C += coff; else { Ch += coff; Cl += coff; }

    const int tid  = threadIdx.x;
    const int warp = tid >> 5;
    const int lane = tid & 31;
    const int wm   = warp & 1;
    const int wn   = warp >> 1;

    wmma::fragment<wmma::accumulator, 16, 16, 16, float> acc[4][WN];
    #pragma unroll
    for (int i = 0; i < 4; i++)
        #pragma unroll
        for (int j = 0; j < WN; j++) wmma::fill_fragment(acc[i][j], 0.0f);

    auto load_stage = [&](int st, int k0) {
        char* base = sm + st * STAGE;
        bf16* dAh = (bf16*)base;
        bf16* dAl = (bf16*)(base + ABYTES);
        bf16* dBh = (bf16*)(base + 2 * ABYTES);
        bf16* dBl = (bf16*)(base + 2 * ABYTES + BBYTES);
        #pragma unroll
        for (int i = 0; i < 4; i++) {         // A hi+lo: 1024 chunks
            int idx = tid + (i << 8);
            int l = idx & 511;
            int r = l >> 2, c = (l & 3) * 8;
            const bf16* src = (idx < 512 ? Ah : Al) + (size_t)(m0 + r) * lda + k0 + c;
            cp_async16((idx < 512 ? dAh : dAl) + r * APITCH + c, src);
        }
        if constexpr (BCOL) {
            #pragma unroll
            for (int i = 0; i < BN / 32; i++) {  // B hi+lo: 8*BN chunks
                int idx = tid + (i << 8);
                int l = idx & (BN * 4 - 1);
                int r = l >> 2, c = (l & 3) * 8;
                const bf16* src = (idx < BN * 4 ? Bh : Bl) + (size_t)(n0 + r) * ldb + k0 + c;
                cp_async16((idx < BN * 4 ? dBh : dBl) + r * APITCH + c, src);
            }
        } else {
            constexpr int CPR = BN / 8;          // 16B chunks per row
            #pragma unroll
            for (int i = 0; i < BN / 32; i++) {
                int idx = tid + (i << 8);
                int l = idx & (BN * 4 - 1);
                int r = l / CPR, c = (l % CPR) * 8;
                const bf16* src = (idx < BN * 4 ? Bh : Bl) + (size_t)(k0 + r) * ldb + n0 + c;
                cp_async16((idx < BN * 4 ? dBh : dBl) + r * BPITCH + c, src);
            }
        }
    };

    int nIter = Kd >> 5;
    if (kmode == 2 && klens) {
        int kl = klens[bb];
        int ni = (kl + 31) >> 5;
        if (ni < nIter) nIter = ni;
    }

    load_stage(0, 0); cp_commit();
    if (nIter > 1) { load_stage(1, 32); cp_commit(); }

    for (int it = 0; it < nIter; ++it) {
        if (it + 1 < nIter) cp_wait1(); else cp_wait0();
        __syncthreads();
        if (it + 2 < nIter) { load_stage((it + 2) % 3, (it + 2) << 5); cp_commit(); }

        char* base = sm + (it % 3) * STAGE;
        const bf16* sAh = (const bf16*)base;
        const bf16* sAl = (const bf16*)(base + ABYTES);
        const bf16* sBh = (const bf16*)(base + 2 * ABYTES);
        const bf16* sBl = (const bf16*)(base + 2 * ABYTES + BBYTES);
        #pragma unroll
        for (int kk = 0; kk < 2; kk++) {
            wmma::fragment<wmma::matrix_a, 16, 16, 16, bf16, wmma::row_major> ah[4], al[4];
            #pragma unroll
            for (int i = 0; i < 4; i++) {
                wmma::load_matrix_sync(ah[i], sAh + (wm * 64 + 16 * i) * APITCH + kk * 16, APITCH);
                wmma::load_matrix_sync(al[i], sAl + (wm * 64 + 16 * i) * APITCH + kk * 16, APITCH);
            }
            #pragma unroll
            for (int j = 0; j < WN; j++) {
                const int ncol = wn * (BN / 4) + 16 * j;
                if constexpr (BCOL) {
                    wmma::fragment<wmma::matrix_b, 16, 16, 16, bf16, wmma::col_major> bh, bl;
                    wmma::load_matrix_sync(bh, sBh + ncol * APITCH + kk * 16, APITCH);
                    wmma::load_matrix_sync(bl, sBl + ncol * APITCH + kk * 16, APITCH);
                    #pragma unroll
                    for (int i = 0; i < 4; i++) {
                        wmma::mma_sync(acc[i][j], ah[i], bh, acc[i][j]);
                        wmma::mma_sync(acc[i][j], al[i], bh, acc[i][j]);
                        wmma::mma_sync(acc[i][j], ah[i], bl, acc[i][j]);
                    }
                } else {
                    wmma::fragment<wmma::matrix_b, 16, 16, 16, bf16, wmma::row_major> bh, bl;
                    wmma::load_matrix_sync(bh, sBh + (kk * 16) * BPITCH + ncol, BPITCH);
                    wmma::load_matrix_sync(bl, sBl + (kk * 16) * BPITCH + ncol, BPITCH);
                    #pragma unroll
                    for (int i = 0; i < 4; i++) {
                        wmma::mma_sync(acc[i][j], ah[i], bh, acc[i][j]);
                        wmma::mma_sync(acc[i][j], al[i], bh, acc[i][j]);
                        wmma::mma_sync(acc[i][j], ah[i], bl, acc[i][j]);
                    }
                }
            }
        }
        __syncthreads();
    }

    if constexpr (OMODE == 0) {
        #pragma unroll
        for (int i = 0; i < 4; i++)
            #pragma unroll
            for (int j = 0; j < WN; j++)
                wmma::store_matrix_sync(
                    C + (size_t)(m0 + wm * 64 + 16 * i) * ldc + n0 + wn * (BN / 4) + 16 * j,
                    acc[i][j], ldc, wmma::mem_row_major);
    } else {
        __syncthreads();
        float* stag = (float*)sm + warp * 2560;  // 64 x 40 floats per warp
        const int bidx = m0 / Lc;
        #pragma unroll
        for (int p = 0; p < WN / 2; p++) {
            #pragma unroll
            for (int i = 0; i < 4; i++)
                #pragma unroll
                for (int jj = 0; jj < 2; jj++)
                    wmma::store_matrix_sync(stag + (16 * i) * 40 + 16 * jj,
                                            acc[i][2 * p + jj], 40, wmma::mem_row_major);
            __syncwarp();
            #pragma unroll
            for (int itr = 0; itr < 16; itr++) {
                int g = lane + itr * 32;
                int r = g >> 3;
                int c = (g & 7) * 4;
                float4 v = *reinterpret_cast<const float4*>(stag + r * 40 + c);
                int gr = m0 + wm * 64 + r;
                int gc = n0 + wn * (BN / 4) + p * 32 + c;
                if constexpr (OMODE == 1) {
                    if (bias) {
                        float4 bv = *reinterpret_cast<const float4*>(&bias[gc]);
                        v.x += bv.x; v.y += bv.y; v.z += bv.z; v.w += bv.w;
                    }
                    split_store4(Ch, Cl, (size_t)gr * ldc + gc, v);
                } else {
                    float4 bv = *reinterpret_cast<const float4*>(&bias[gc]);
                    float4 g1 = *reinterpret_cast<const float4*>(&t_emb[(size_t)(bidx * 3 + 2) * Dc + gc]);
                    float4 g2 = *reinterpret_cast<const float4*>(&ssg[2 * Dc + gc]);
                    float4 o;
                    o.x = (v.x + bv.x) * (g1.x + g2.x);
                    o.y = (v.y + bv.y) * (g1.y + g2.y);
                    o.z = (v.z + bv.z) * (g1.z + g2.z);
                    o.w = (v.w + bv.w) * (g1.w + g2.w);
                    *reinterpret_cast<float4*>(&C[(size_t)gr * ldc + gc]) = o;
                }
            }
            __syncwarp();
        }
    }
}

// ---------------------------------------------------------------------------
// LayerNorm of x -> xk hi/lo
// ---------------------------------------------------------------------------
__global__ void ln_x_kernel(const float* __restrict__ x,
                            const float* __restrict__ w,
                            const float* __restrict__ b,
                            bf16* __restrict__ out_hi, bf16* __restrict__ out_lo) {
    __shared__ float red[33];
    const int row = blockIdx.x;
    const size_t base = (size_t)row * KVc;
    const int t = threadIdx.x;
    const int c0 = t * 4, c1 = c0 + 1024;

    float4 v0 = *reinterpret_cast<const float4*>(&x[base + c0]);
    float4 v1 = *reinterpret_cast<const float4*>(&x[base + c1]);
    float s = v0.x + v0.y + v0.z + v0.w + v1.x + v1.y + v1.z + v1.w;
    float mean = block_sum256(s, red) * (1.0f / KVc);
    float d0x = v0.x - mean, d0y = v0.y - mean, d0z = v0.z - mean, d0w = v0.w - mean;
    float d1x = v1.x - mean, d1y = v1.y - mean, d1z = v1.z - mean, d1w = v1.w - mean;
    float sq = d0x*d0x + d0y*d0y + d0z*d0z + d0w*d0w + d1x*d1x + d1y*d1y + d1z*d1z + d1w*d1w;
    float var = block_sum256(sq, red) * (1.0f / KVc);
    float rstd = rsqrtf(var + 1e-5f);

    float4 w0 = *reinterpret_cast<const float4*>(&w[c0]);
    float4 w1 = *reinterpret_cast<const float4*>(&w[c1]);
    float4 b0 = *reinterpret_cast<const float4*>(&b[c0]);
    float4 b1 = *reinterpret_cast<const float4*>(&b[c1]);
    split_store4(out_hi, out_lo, base + c0,
        make_float4(d0x*rstd*w0.x + b0.x, d0y*rstd*w0.y + b0.y,
                    d0z*rstd*w0.z + b0.z, d0w*rstd*w0.w + b0.w));
    split_store4(out_hi, out_lo, base + c1,
        make_float4(d1x*rstd*w1.x + b1.x, d1y*rstd*w1.y + b1.y,
                    d1z*rstd*w1.z + b1.z, d1w*rstd*w1.w + b1.w));
}

// ---------------------------------------------------------------------------
// LayerNorm of latents + adaLN modulation -> lat hi/lo
// ---------------------------------------------------------------------------
__global__ void ln_lat_kernel(const float* __restrict__ latents,
                              const float* __restrict__ t_emb,
                              const float* __restrict__ ssg,
                              bf16* __restrict__ out_hi, bf16* __restrict__ out_lo) {
    __shared__ float red[33];
    const int row = blockIdx.x;
    const int bidx = row / Lc;
    const size_t base = (size_t)row * Dc;
    const int t = threadIdx.x;
    const int c0 = t * 4, c1 = c0 + 1024;

    float4 v0 = *reinterpret_cast<const float4*>(&latents[base + c0]);
    float4 v1 = *reinterpret_cast<const float4*>(&latents[base + c1]);
    float s = v0.x + v0.y + v0.z + v0.w + v1.x + v1.y + v1.z + v1.w;
    float mean = block_sum256(s, red) * (1.0f / Dc);
    float d0x = v0.x - mean, d0y = v0.y - mean, d0z = v0.z - mean, d0w = v0.w - mean;
    float d1x = v1.x - mean, d1y = v1.y - mean, d1z = v1.z - mean, d1w = v1.w - mean;
    float sq = d0x*d0x + d0y*d0y + d0z*d0z + d0w*d0w + d1x*d1x + d1y*d1y + d1z*d1z + d1w*d1w;
    float var = block_sum256(sq, red) * (1.0f / Dc);
    float rstd = rsqrtf(var + 1e-5f);

    const float* sh_t = t_emb + (size_t)(bidx * 3 + 0) * Dc;
    const float* sc_t = t_emb + (size_t)(bidx * 3 + 1) * Dc;

    #pragma unroll
    for (int half = 0; half < 2; half++) {
        int c = (half == 0) ? c0 : c1;
        float dv[4] = { (half ? d1x : d0x), (half ? d1y : d0y),
                        (half ? d1z : d0z), (half ? d1w : d0w) };
        float4 sht = *reinterpret_cast<const float4*>(&sh_t[c]);
        float4 sct = *reinterpret_cast<const float4*>(&sc_t[c]);
        float4 shs = *reinterpret_cast<const float4*>(&ssg[c]);
        float4 scs = *reinterpret_cast<const float4*>(&ssg[Dc + c]);
        float4 o;
        o.x = dv[0]*rstd * (1.0f + sct.x + scs.x) + sht.x + shs.x;
        o.y = dv[1]*rstd * (1.0f + sct.y + scs.y) + sht.y + shs.y;
        o.z = dv[2]*rstd * (1.0f + sct.z + scs.z) + sht.z + shs.z;
        o.w = dv[3]*rstd * (1.0f + sct.w + scs.w) + sht.w + shs.w;
        split_store4(out_hi, out_lo, base + c, o);
    }
}

// ---------------------------------------------------------------------------
// Masked softmax over K=1024; alpha on read; writes bf16 hi/lo probabilities.
// ---------------------------------------------------------------------------
__global__ void softmax_kernel(const float* __restrict__ sc,
                               const int* __restrict__ k_lens,
                               bf16* __restrict__ ph, bf16* __restrict__ pl) {
    __shared__ float red[33];
    const int row = blockIdx.x;
    const int bidx = row / (Hc * Lc);
    const int klen = k_lens[bidx];
    const float* p = sc + (size_t)row * Kc;
    const int t = threadIdx.x;
    const int j0 = t * 4;
    const float alpha = 0.08838834764831845f;

    float4 v = *reinterpret_cast<const float4*>(&p[j0]);
    float vv[4] = { v.x, v.y, v.z, v.w };
    float mx = -1e30f;
    #pragma unroll
    for (int i = 0; i < 4; i++) {
        vv[i] = (j0 + i < klen) ? vv[i] * alpha : -1e30f;
        mx = fmaxf(mx, vv[i]);
    }
    mx = block_max256(mx, red);
    float e[4]; float s = 0.0f;
    #pragma unroll
    for (int i = 0; i < 4; i++) {
        e[i] = (j0 + i < klen) ? expf(vv[i] - mx) : 0.0f;
        s += e[i];
    }
    s = block_sum256(s, red);
    float inv = 1.0f / s;
    split_store4(ph, pl, (size_t)row * Kc + j0,
                 make_float4(e[0] * inv, e[1] * inv, e[2] * inv, e[3] * inv));
}

// ---------------------------------------------------------------------------
// Zero attention-output rows where l >= q_lens[b]
// ---------------------------------------------------------------------------
__global__ void qmask_kernel(bf16* __restrict__ ah, bf16* __restrict__ al,
                             const int* __restrict__ q_lens) {
    const int row = blockIdx.x;
    const int bidx = row / Lc;
    const int l = row - bidx * Lc;
    if (l < q_lens[bidx]) return;
    const int t = threadIdx.x;
    float4 z = make_float4(0.f, 0.f, 0.f, 0.f);
    *reinterpret_cast<float4*>(&ah[(size_t)row * Dc + t * 8]) = z;
    *reinterpret_cast<float4*>(&al[(size_t)row * Dc + t * 8]) = z;
}

// ---------------------------------------------------------------------------
// Launch
// ---------------------------------------------------------------------------
extern "C" void kernel_launch(void* const* d_in, const int* in_sizes, int n_in,
                              void* d_out, int out_size) {
    (void)in_sizes; (void)n_in; (void)out_size;
    const float* x       = (const float*)d_in[0];
    const float* latents = (const float*)d_in[1];
    const float* t_emb   = (const float*)d_in[2];
    const int*   q_lens  = (const int*)  d_in[3];
    const int*   k_lens  = (const int*)  d_in[4];
    const float* ln_kv_w = (const float*)d_in[5];
    const float* ln_kv_b = (const float*)d_in[6];
    const float* ssg     = (const float*)d_in[7];
    const float* Wq      = (const float*)d_in[8];
    const float* bq      = (const float*)d_in[9];
    const float* Wkv     = (const float*)d_in[10];
    const float* bkv     = (const float*)d_in[11];
    const float* Wo      = (const float*)d_in[12];
    const float* bo      = (const float*)d_in[13];
    float* out = (float*)d_out;

    bf16 *xk_h, *xk_l, *lat_h, *lat_l, *q_h, *q_l, *kv_h, *kv_l;
    bf16 *p_h, *p_l, *at_h, *at_l, *wq_h, *wq_l, *wkv_h, *wkv_l, *wo_h, *wo_l;
    float* sc;
    cudaGetSymbolAddress((void**)&xk_h, g_xk_hi);   cudaGetSymbolAddress((void**)&xk_l, g_xk_lo);
    cudaGetSymbolAddress((void**)&lat_h, g_lat_hi); cudaGetSymbolAddress((void**)&lat_l, g_lat_lo);
    cudaGetSymbolAddress((void**)&q_h, g_q_hi);     cudaGetSymbolAddress((void**)&q_l, g_q_lo);
    cudaGetSymbolAddress((void**)&kv_h, g_kv_hi);   cudaGetSymbolAddress((void**)&kv_l, g_kv_lo);
    cudaGetSymbolAddress((void**)&p_h, g_p_hi);     cudaGetSymbolAddress((void**)&p_l, g_p_lo);
    cudaGetSymbolAddress((void**)&at_h, g_at_hi);   cudaGetSymbolAddress((void**)&at_l, g_at_lo);
    cudaGetSymbolAddress((void**)&wq_h, g_wq_hi);   cudaGetSymbolAddress((void**)&wq_l, g_wq_lo);
    cudaGetSymbolAddress((void**)&wkv_h, g_wkv_hi); cudaGetSymbolAddress((void**)&wkv_l, g_wkv_lo);
    cudaGetSymbolAddress((void**)&wo_h, g_wo_hi);   cudaGetSymbolAddress((void**)&wo_l, g_wo_lo);
    cudaGetSymbolAddress((void**)&sc, g_scores);

    // dynamic smem sizes per instantiation (3 stages)
    constexpr int SMEM_F256 = 3 * (2 * 128 * 40 * 2 + 2 * 32 * 264 * 2);  // 162816
    constexpr int SMEM_T256 = 3 * (2 * 128 * 40 * 2 + 2 * 256 * 40 * 2); // 184320
    constexpr int SMEM_F128 = 3 * (2 * 128 * 40 * 2 + 2 * 32 * 136 * 2);  // 113664
    cudaFuncSetAttribute(gemm_ks<false, 256, 1>, cudaFuncAttributeMaxDynamicSharedMemorySize, SMEM_F256);
    cudaFuncSetAttribute(gemm_ks<false, 256, 2>, cudaFuncAttributeMaxDynamicSharedMemorySize, SMEM_F256);
    cudaFuncSetAttribute(gemm_ks<true, 256, 0>,  cudaFuncAttributeMaxDynamicSharedMemorySize, SMEM_T256);
    cudaFuncSetAttribute(gemm_ks<false, 128, 1>, cudaFuncAttributeMaxDynamicSharedMemorySize, SMEM_F128);

    // Launch order puts the kv GEMM at index 3 (the ncu capture slot).
    split_kernel<<<2048, 256>>>(Wkv, wkv_h, wkv_l, KVc * 2 * Dc / 4);          // 0
    ln_x_kernel<<<Bc * Kc, 256>>>(x, ln_kv_w, ln_kv_b, xk_h, xk_l);            // 1
    split_kernel<<<2048, 256>>>(Wq,  wq_h,  wq_l,  Dc * Dc / 4);               // 2

    // 3) kv = xk @ Wkv + bkv
    gemm_ks<false, 256, 1><<<dim3(2 * Dc / 256, (Bc * Kc) / 128, 1), 256, SMEM_F256>>>(
        xk_h, xk_l, wkv_h, wkv_l, nullptr, kv_h, kv_l, bkv, nullptr, nullptr,
        nullptr, 0,
        KVc, KVc, 2 * Dc, 2 * Dc, 0, 0, 0, 0, 0, 0, 1);

    ln_lat_kernel<<<Bc * Lc, 256>>>(latents, t_emb, ssg, lat_h, lat_l);        // 4

    // 5) q = lat @ Wq + bq
    gemm_ks<false, 256, 1><<<dim3(Dc / 256, (Bc * Lc) / 128, 1), 256, SMEM_F256>>>(
        lat_h, lat_l, wq_h, wq_l, nullptr, q_h, q_l, bq, nullptr, nullptr,
        nullptr, 0,
        Dc, Dc, Dc, Dc, 0, 0, 0, 0, 0, 0, 1);

    split_kernel<<<2048, 256>>>(Wo,  wo_h,  wo_l,  Dc * Dc / 4);               // 6

    // 7) scores[b,h] = q[b,:,h,:] @ k[b,:,h,:]^T  (skip fully-masked N tiles)
    gemm_ks<true, 256, 0><<<dim3(Kc / 256, Lc / 128, Bc * Hc), 256, SMEM_T256>>>(
        q_h, q_l, kv_h, kv_l, sc, nullptr, nullptr, nullptr, nullptr, nullptr,
        k_lens, 1,
        Cc, Dc, 2 * Dc, Kc,
        (long long)Lc * Dc, (long long)Cc,
        (long long)Kc * 2 * Dc, (long long)Cc,
        (long long)Hc * Lc * Kc, (long long)Lc * Kc, Hc);

    // 8) masked softmax -> p hi/lo
    softmax_kernel<<<Bc * Hc * Lc, 256>>>(sc, k_lens, p_h, p_l);

    // 9) attn_out = p @ v  (K-loop shortened to klen)
    gemm_ks<false, 128, 1><<<dim3(1, Lc / 128, Bc * Hc), 256, SMEM_F128>>>(
        p_h, p_l, kv_h + Dc, kv_l + Dc, nullptr, at_h, at_l, nullptr, nullptr, nullptr,
        k_lens, 2,
        Kc, Kc, 2 * Dc, Dc,
        (long long)Hc * Lc * Kc, (long long)Lc * Kc,
        (long long)Kc * 2 * Dc, (long long)Cc,
        (long long)Lc * Dc, (long long)Cc, Hc);

    // 10) qmask
    qmask_kernel<<<Bc * Lc, 256>>>(at_h, at_l, q_lens);

    // 11) out = (at @ Wo + bo) * gate
    gemm_ks<false, 256, 2><<<dim3(Dc / 256, (Bc * Lc) / 128, 1), 256, SMEM_F256>>>(
        at_h, at_l, wo_h, wo_l, out, nullptr, nullptr, bo, t_emb, ssg,
        nullptr, 0,
        Dc, Dc, Dc, Dc, 0, 0, 0, 0, 0, 0, 1);
}

// round 5
// speedup vs baseline: 1.4505x; 1.0985x over previous
#include <cuda_runtime.h>
#include <cuda_bf16.h>
#include <mma.h>
#include <cstdint>

using namespace nvcuda;
typedef __nv_bfloat16 bf16;

// Problem dims
constexpr int Bc  = 4;
constexpr int Lc  = 512;
constexpr int Dc  = 2048;
constexpr int Hc  = 16;
constexpr int Cc  = 128;
constexpr int KVc = 2048;
constexpr int Kc  = 1024;   // T*LA

// ---------------------------------------------------------------------------
// Scratch (device globals — allocation-free rule)
// ---------------------------------------------------------------------------
__device__ bf16  g_xk_hi[(size_t)Bc * Kc * KVc];
__device__ bf16  g_xk_lo[(size_t)Bc * Kc * KVc];
__device__ bf16  g_lat_hi[(size_t)Bc * Lc * Dc];
__device__ bf16  g_lat_lo[(size_t)Bc * Lc * Dc];
__device__ bf16  g_q_hi[(size_t)Bc * Lc * Dc];
__device__ bf16  g_q_lo[(size_t)Bc * Lc * Dc];
__device__ bf16  g_kv_hi[(size_t)Bc * Kc * 2 * Dc];
__device__ bf16  g_kv_lo[(size_t)Bc * Kc * 2 * Dc];
__device__ float g_scores[(size_t)Bc * Hc * Lc * Kc];
__device__ bf16  g_p_hi[(size_t)Bc * Hc * Lc * Kc];
__device__ bf16  g_p_lo[(size_t)Bc * Hc * Lc * Kc];
__device__ bf16  g_at_hi[(size_t)Bc * Lc * Dc];
__device__ bf16  g_at_lo[(size_t)Bc * Lc * Dc];
__device__ bf16  g_wq_hi[(size_t)Dc * Dc];
__device__ bf16  g_wq_lo[(size_t)Dc * Dc];
__device__ bf16  g_wkv_hi[(size_t)KVc * 2 * Dc];
__device__ bf16  g_wkv_lo[(size_t)KVc * 2 * Dc];
__device__ bf16  g_wo_hi[(size_t)Dc * Dc];
__device__ bf16  g_wo_lo[(size_t)Dc * Dc];

// ---------------------------------------------------------------------------
// Helpers
// ---------------------------------------------------------------------------
__device__ __forceinline__ void cp_async16(void* smem_dst, const void* gmem_src) {
    unsigned s = (unsigned)__cvta_generic_to_shared(smem_dst);
    asm volatile("cp.async.cg.shared.global [%0], [%1], 16;\n" :: "r"(s), "l"(gmem_src));
}
__device__ __forceinline__ void cp_commit() { asm volatile("cp.async.commit_group;\n"); }
__device__ __forceinline__ void cp_wait0()  { asm volatile("cp.async.wait_group 0;\n"); }
__device__ __forceinline__ void cp_wait1()  { asm volatile("cp.async.wait_group 1;\n"); }

struct __align__(8) bf4 { bf16 v[4]; };
__device__ __forceinline__ void split_store4(bf16* hi, bf16* lo, size_t off, float4 f) {
    bf4 H, L;
    float ff[4] = { f.x, f.y, f.z, f.w };
    #pragma unroll
    for (int e = 0; e < 4; e++) {
        bf16 h = __float2bfloat16(ff[e]);
        H.v[e] = h;
        L.v[e] = __float2bfloat16(ff[e] - __bfloat162float(h));
    }
    *reinterpret_cast<bf4*>(hi + off) = H;
    *reinterpret_cast<bf4*>(lo + off) = L;
}

__device__ __forceinline__ float warp_sum(float v) {
    #pragma unroll
    for (int o = 16; o > 0; o >>= 1) v += __shfl_xor_sync(0xffffffffu, v, o);
    return v;
}
__device__ __forceinline__ float warp_max(float v) {
    #pragma unroll
    for (int o = 16; o > 0; o >>= 1) v = fmaxf(v, __shfl_xor_sync(0xffffffffu, v, o));
    return v;
}
__device__ __forceinline__ float block_sum256(float v, float* red) {
    int lane = threadIdx.x & 31, w = threadIdx.x >> 5;
    v = warp_sum(v);
    if (lane == 0) red[w] = v;
    __syncthreads();
    if (w == 0) {
        float t = (lane < 8) ? red[lane] : 0.0f;
        t = warp_sum(t);
        if (lane == 0) red[32] = t;
    }
    __syncthreads();
    float r = red[32];
    __syncthreads();
    return r;
}
__device__ __forceinline__ float block_max256(float v, float* red) {
    int lane = threadIdx.x & 31, w = threadIdx.x >> 5;
    v = warp_max(v);
    if (lane == 0) red[w] = v;
    __syncthreads();
    if (w == 0) {
        float t = (lane < 8) ? red[lane] : -1e30f;
        t = warp_max(t);
        if (lane == 0) red[32] = t;
    }
    __syncthreads();
    float r = red[32];
    __syncthreads();
    return r;
}

// ---------------------------------------------------------------------------
// fp32 -> bf16 hi/lo splitter (weights)
// ---------------------------------------------------------------------------
__global__ void split_kernel(const float* __restrict__ W,
                             bf16* __restrict__ hi, bf16* __restrict__ lo,
                             int total4) {
    int i = blockIdx.x * blockDim.x + threadIdx.x;
    const int stride = gridDim.x * blockDim.x;
    for (; i < total4; i += stride) {
        float4 v = reinterpret_cast<const float4*>(W)[i];
        split_store4(hi, lo, (size_t)i * 4, v);
    }
}

// ---------------------------------------------------------------------------
// bf16x3 GEMM, pre-split operands, BK=64, 2-stage cp.async double buffer.
//   BCOL=false: C = A @ B       (B row-major Kd x N)
//   BCOL=true : C = A @ B^T     (B row-major N x Kd)
// CTA tile 128 x BN, 256 threads, 8 warps (2 x 4): warp tile 64 x (BN/4).
// OMODE: 0 fp32 store; 1 bf16 hi/lo (+bias); 2 (acc+bias)*gate fp32.
// kmode: 0 none; 1 skip CTA if n0 >= k_lens[b]; 2 shorten K to k_lens[b].
// ---------------------------------------------------------------------------
template <bool BCOL, int BN, int OMODE>
__global__ void __launch_bounds__(256)
gemm_ks(const bf16* __restrict__ Ah, const bf16* __restrict__ Al,
        const bf16* __restrict__ Bh, const bf16* __restrict__ Bl,
        float* __restrict__ C, bf16* __restrict__ Ch, bf16* __restrict__ Cl,
        const float* __restrict__ bias,
        const float* __restrict__ t_emb, const float* __restrict__ ssg,
        const int* __restrict__ klens, int kmode,
        int Kd, int lda, int ldb, int ldc,
        long long asb, long long ash,
        long long bsb, long long bsh,
        long long csb, long long csh, int HB) {
    extern __shared__ char sm[];
    constexpr int APITCH = 72;                       // bf16 pitch, BK=64 (+8 pad)
    constexpr int BPITCH = BCOL ? 72 : (BN + 8);
    constexpr int ABYTES = 128 * APITCH * 2;         // 18432 per A slice
    constexpr int BBYTES = BCOL ? BN * 72 * 2 : 64 * (BN + 8) * 2;
    constexpr int STAGE  = 2 * ABYTES + 2 * BBYTES;
    constexpr int WN     = BN / 64;                  // wmma j-tiles per warp

    const int z  = blockIdx.z;
    const int bb = z / HB, hh = z - bb * HB;
    const int n0 = blockIdx.x * BN;
    const int m0 = blockIdx.y * 128;

    if (kmode == 1 && klens && n0 >= klens[bb]) return;  // fully masked tile

    Ah += (size_t)bb * asb + (size_t)hh * ash;
    Al += (size_t)bb * asb + (size_t)hh * ash;
    Bh += (size_t)bb * bsb + (size_t)hh * bsh;
    Bl += (size_t)bb * bsb + (size_t)hh * bsh;
    const long long coff = (long long)bb * csb + (long long)hh * csh;
    if (OMODE == 0 || OMODE == 2) C += coff; else { Ch += coff; Cl += coff; }

    const int tid  = threadIdx.x;
    const int warp = tid >> 5;
    const int lane = tid & 31;
    const int wm   = warp & 1;
    const int wn   = warp >> 1;

    wmma::fragment<wmma::accumulator, 16, 16, 16, float> acc[4][WN];
    #pragma unroll
    for (int i = 0; i < 4; i++)
        #pragma unroll
        for (int j = 0; j < WN; j++) wmma::fill_fragment(acc[i][j], 0.0f);

    auto load_stage = [&](int st, int k0) {
        char* base = sm + st * STAGE;
        bf16* dAh = (bf16*)base;
        bf16* dAl = (bf16*)(base + ABYTES);
        bf16* dBh = (bf16*)(base + 2 * ABYTES);
        bf16* dBl = (bf16*)(base + 2 * ABYTES + BBYTES);
        // A hi+lo: 128 rows x 64 cols -> 1024 16B-chunks per array
        #pragma unroll
        for (int i = 0; i < 8; i++) {
            int idx = tid + (i << 8);
            int l = idx & 1023;
            int r = l >> 3, c = (l & 7) * 8;
            const bf16* src = (idx < 1024 ? Ah : Al) + (size_t)(m0 + r) * lda + k0 + c;
            cp_async16((idx < 1024 ? dAh : dAl) + r * APITCH + c, src);
        }
        if constexpr (BCOL) {
            // B hi+lo: BN rows x 64 cols
            #pragma unroll
            for (int i = 0; i < BN / 16; i++) {
                int idx = tid + (i << 8);
                int l = idx & (BN * 8 - 1);
                int r = l >> 3, c = (l & 7) * 8;
                const bf16* src = (idx < BN * 8 ? Bh : Bl) + (size_t)(n0 + r) * ldb + k0 + c;
                cp_async16((idx < BN * 8 ? dBh : dBl) + r * APITCH + c, src);
            }
        } else {
            // B hi+lo: 64 rows x BN cols
            constexpr int CPR = BN / 8;              // 16B chunks per row
            #pragma unroll
            for (int i = 0; i < BN / 16; i++) {
                int idx = tid + (i << 8);
                int l = idx & (8 * BN - 1);
                int r = l / CPR, c = (l % CPR) * 8;
                const bf16* src = (idx < 8 * BN ? Bh : Bl) + (size_t)(k0 + r) * ldb + n0 + c;
                cp_async16((idx < 8 * BN ? dBh : dBl) + r * BPITCH + c, src);
            }
        }
    };

    int nIter = Kd >> 6;
    if (kmode == 2 && klens) {
        int kl = klens[bb];
        int ni = (kl + 63) >> 6;
        if (ni < nIter) nIter = ni;
    }

    load_stage(0, 0); cp_commit();
    if (nIter > 1) { load_stage(1, 64); cp_commit(); }

    for (int it = 0; it < nIter; ++it) {
        if (it + 1 < nIter) cp_wait1(); else cp_wait0();
        __syncthreads();

        char* base = sm + (it & 1) * STAGE;
        const bf16* sAh = (const bf16*)base;
        const bf16* sAl = (const bf16*)(base + ABYTES);
        const bf16* sBh = (const bf16*)(base + 2 * ABYTES);
        const bf16* sBl = (const bf16*)(base + 2 * ABYTES + BBYTES);
        #pragma unroll
        for (int kk = 0; kk < 4; kk++) {
            wmma::fragment<wmma::matrix_a, 16, 16, 16, bf16, wmma::row_major> ah[4], al[4];
            #pragma unroll
            for (int i = 0; i < 4; i++) {
                wmma::load_matrix_sync(ah[i], sAh + (wm * 64 + 16 * i) * APITCH + kk * 16, APITCH);
                wmma::load_matrix_sync(al[i], sAl + (wm * 64 + 16 * i) * APITCH + kk * 16, APITCH);
            }
            #pragma unroll
            for (int j = 0; j < WN; j++) {
                const int ncol = wn * (BN / 4) + 16 * j;
                if constexpr (BCOL) {
                    wmma::fragment<wmma::matrix_b, 16, 16, 16, bf16, wmma::col_major> bh, bl;
                    wmma::load_matrix_sync(bh, sBh + ncol * APITCH + kk * 16, APITCH);
                    wmma::load_matrix_sync(bl, sBl + ncol * APITCH + kk * 16, APITCH);
                    #pragma unroll
                    for (int i = 0; i < 4; i++) {
                        wmma::mma_sync(acc[i][j], ah[i], bh, acc[i][j]);
                        wmma::mma_sync(acc[i][j], al[i], bh, acc[i][j]);
                        wmma::mma_sync(acc[i][j], ah[i], bl, acc[i][j]);
                    }
                } else {
                    wmma::fragment<wmma::matrix_b, 16, 16, 16, bf16, wmma::row_major> bh, bl;
                    wmma::load_matrix_sync(bh, sBh + (kk * 16) * BPITCH + ncol, BPITCH);
                    wmma::load_matrix_sync(bl, sBl + (kk * 16) * BPITCH + ncol, BPITCH);
                    #pragma unroll
                    for (int i = 0; i < 4; i++) {
                        wmma::mma_sync(acc[i][j], ah[i], bh, acc[i][j]);
                        wmma::mma_sync(acc[i][j], al[i], bh, acc[i][j]);
                        wmma::mma_sync(acc[i][j], ah[i], bl, acc[i][j]);
                    }
                }
            }
        }

        if (it + 2 < nIter) {
            __syncthreads();                 // all warps done reading buffer (it&1)
            load_stage(it & 1, (it + 2) << 6);
            cp_commit();
        }
    }

    if constexpr (OMODE == 0) {
        #pragma unroll
        for (int i = 0; i < 4; i++)
            #pragma unroll
            for (int j = 0; j < WN; j++)
                wmma::store_matrix_sync(
                    C + (size_t)(m0 + wm * 64 + 16 * i) * ldc + n0 + wn * (BN / 4) + 16 * j,
                    acc[i][j], ldc, wmma::mem_row_major);
    } else {
        __syncthreads();
        float* stag = (float*)sm + warp * 2560;  // 64 x 40 floats per warp
        const int bidx = m0 / Lc;
        #pragma unroll
        for (int p = 0; p < WN / 2; p++) {
            #pragma unroll
            for (int i = 0; i < 4; i++)
                #pragma unroll
                for (int jj = 0; jj < 2; jj++)
                    wmma::store_matrix_sync(stag + (16 * i) * 40 + 16 * jj,
                                            acc[i][2 * p + jj], 40, wmma::mem_row_major);
            __syncwarp();
            #pragma unroll
            for (int itr = 0; itr < 16; itr++) {
                int g = lane + itr * 32;
                int r = g >> 3;
                int c = (g & 7) * 4;
                float4 v = *reinterpret_cast<const float4*>(stag + r * 40 + c);
                int gr = m0 + wm * 64 + r;
                int gc = n0 + wn * (BN / 4) + p * 32 + c;
                if constexpr (OMODE == 1) {
                    if (bias) {
                        float4 bv = *reinterpret_cast<const float4*>(&bias[gc]);
                        v.x += bv.x; v.y += bv.y; v.z += bv.z; v.w += bv.w;
                    }
                    split_store4(Ch, Cl, (size_t)gr * ldc + gc, v);
                } else {
                    float4 bv = *reinterpret_cast<const float4*>(&bias[gc]);
                    float4 g1 = *reinterpret_cast<const float4*>(&t_emb[(size_t)(bidx * 3 + 2) * Dc + gc]);
                    float4 g2 = *reinterpret_cast<const float4*>(&ssg[2 * Dc + gc]);
                    float4 o;
                    o.x = (v.x + bv.x) * (g1.x + g2.x);
                    o.y = (v.y + bv.y) * (g1.y + g2.y);
                    o.z = (v.z + bv.z) * (g1.z + g2.z);
                    o.w = (v.w + bv.w) * (g1.w + g2.w);
                    *reinterpret_cast<float4*>(&C[(size_t)gr * ldc + gc]) = o;
                }
            }
            __syncwarp();
        }
    }
}

// ---------------------------------------------------------------------------
// LayerNorm of x -> xk hi/lo
// ---------------------------------------------------------------------------
__global__ void ln_x_kernel(const float* __restrict__ x,
                            const float* __restrict__ w,
                            const float* __restrict__ b,
                            bf16* __restrict__ out_hi, bf16* __restrict__ out_lo) {
    __shared__ float red[33];
    const int row = blockIdx.x;
    const size_t base = (size_t)row * KVc;
    const int t = threadIdx.x;
    const int c0 = t * 4, c1 = c0 + 1024;

    float4 v0 = *reinterpret_cast<const float4*>(&x[base + c0]);
    float4 v1 = *reinterpret_cast<const float4*>(&x[base + c1]);
    float s = v0.x + v0.y + v0.z + v0.w + v1.x + v1.y + v1.z + v1.w;
    float mean = block_sum256(s, red) * (1.0f / KVc);
    float d0x = v0.x - mean, d0y = v0.y - mean, d0z = v0.z - mean, d0w = v0.w - mean;
    float d1x = v1.x - mean, d1y = v1.y - mean, d1z = v1.z - mean, d1w = v1.w - mean;
    float sq = d0x*d0x + d0y*d0y + d0z*d0z + d0w*d0w + d1x*d1x + d1y*d1y + d1z*d1z + d1w*d1w;
    float var = block_sum256(sq, red) * (1.0f / KVc);
    float rstd = rsqrtf(var + 1e-5f);

    float4 w0 = *reinterpret_cast<const float4*>(&w[c0]);
    float4 w1 = *reinterpret_cast<const float4*>(&w[c1]);
    float4 b0 = *reinterpret_cast<const float4*>(&b[c0]);
    float4 b1 = *reinterpret_cast<const float4*>(&b[c1]);
    split_store4(out_hi, out_lo, base + c0,
        make_float4(d0x*rstd*w0.x + b0.x, d0y*rstd*w0.y + b0.y,
                    d0z*rstd*w0.z + b0.z, d0w*rstd*w0.w + b0.w));
    split_store4(out_hi, out_lo, base + c1,
        make_float4(d1x*rstd*w1.x + b1.x, d1y*rstd*w1.y + b1.y,
                    d1z*rstd*w1.z + b1.z, d1w*rstd*w1.w + b1.w));
}

// ---------------------------------------------------------------------------
// LayerNorm of latents + adaLN modulation -> lat hi/lo
// ---------------------------------------------------------------------------
__global__ void ln_lat_kernel(const float* __restrict__ latents,
                              const float* __restrict__ t_emb,
                              const float* __restrict__ ssg,
                              bf16* __restrict__ out_hi, bf16* __restrict__ out_lo) {
    __shared__ float red[33];
    const int row = blockIdx.x;
    const int bidx = row / Lc;
    const size_t base = (size_t)row * Dc;
    const int t = threadIdx.x;
    const int c0 = t * 4, c1 = c0 + 1024;

    float4 v0 = *reinterpret_cast<const float4*>(&latents[base + c0]);
    float4 v1 = *reinterpret_cast<const float4*>(&latents[base + c1]);
    float s = v0.x + v0.y + v0.z + v0.w + v1.x + v1.y + v1.z + v1.w;
    float mean = block_sum256(s, red) * (1.0f / Dc);
    float d0x = v0.x - mean, d0y = v0.y - mean, d0z = v0.z - mean, d0w = v0.w - mean;
    float d1x = v1.x - mean, d1y = v1.y - mean, d1z = v1.z - mean, d1w = v1.w - mean;
    float sq = d0x*d0x + d0y*d0y + d0z*d0z + d0w*d0w + d1x*d1x + d1y*d1y + d1z*d1z + d1w*d1w;
    float var = block_sum256(sq, red) * (1.0f / Dc);
    float rstd = rsqrtf(var + 1e-5f);

    const float* sh_t = t_emb + (size_t)(bidx * 3 + 0) * Dc;
    const float* sc_t = t_emb + (size_t)(bidx * 3 + 1) * Dc;

    #pragma unroll
    for (int half = 0; half < 2; half++) {
        int c = (half == 0) ? c0 : c1;
        float dv[4] = { (half ? d1x : d0x), (half ? d1y : d0y),
                        (half ? d1z : d0z), (half ? d1w : d0w) };
        float4 sht = *reinterpret_cast<const float4*>(&sh_t[c]);
        float4 sct = *reinterpret_cast<const float4*>(&sc_t[c]);
        float4 shs = *reinterpret_cast<const float4*>(&ssg[c]);
        float4 scs = *reinterpret_cast<const float4*>(&ssg[Dc + c]);
        float4 o;
        o.x = dv[0]*rstd * (1.0f + sct.x + scs.x) + sht.x + shs.x;
        o.y = dv[1]*rstd * (1.0f + sct.y + scs.y) + sht.y + shs.y;
        o.z = dv[2]*rstd * (1.0f + sct.z + scs.z) + sht.z + shs.z;
        o.w = dv[3]*rstd * (1.0f + sct.w + scs.w) + sht.w + shs.w;
        split_store4(out_hi, out_lo, base + c, o);
    }
}

// ---------------------------------------------------------------------------
// Masked softmax over K=1024; alpha on read; writes bf16 hi/lo probabilities.
// ---------------------------------------------------------------------------
__global__ void softmax_kernel(const float* __restrict__ sc,
                               const int* __restrict__ k_lens,
                               bf16* __restrict__ ph, bf16* __restrict__ pl) {
    __shared__ float red[33];
    const int row = blockIdx.x;
    const int bidx = row / (Hc * Lc);
    const int klen = k_lens[bidx];
    const float* p = sc + (size_t)row * Kc;
    const int t = threadIdx.x;
    const int j0 = t * 4;
    const float alpha = 0.08838834764831845f;

    float4 v = *reinterpret_cast<const float4*>(&p[j0]);
    float vv[4] = { v.x, v.y, v.z, v.w };
    float mx = -1e30f;
    #pragma unroll
    for (int i = 0; i < 4; i++) {
        vv[i] = (j0 + i < klen) ? vv[i] * alpha : -1e30f;
        mx = fmaxf(mx, vv[i]);
    }
    mx = block_max256(mx, red);
    float e[4]; float s = 0.0f;
    #pragma unroll
    for (int i = 0; i < 4; i++) {
        e[i] = (j0 + i < klen) ? expf(vv[i] - mx) : 0.0f;
        s += e[i];
    }
    s = block_sum256(s, red);
    float inv = 1.0f / s;
    split_store4(ph, pl, (size_t)row * Kc + j0,
                 make_float4(e[0] * inv, e[1] * inv, e[2] * inv, e[3] * inv));
}

// ---------------------------------------------------------------------------
// Zero attention-output rows where l >= q_lens[b]
// ---------------------------------------------------------------------------
__global__ void qmask_kernel(bf16* __restrict__ ah, bf16* __restrict__ al,
                             const int* __restrict__ q_lens) {
    const int row = blockIdx.x;
    const int bidx = row / Lc;
    const int l = row - bidx * Lc;
    if (l < q_lens[bidx]) return;
    const int t = threadIdx.x;
    float4 z = make_float4(0.f, 0.f, 0.f, 0.f);
    *reinterpret_cast<float4*>(&ah[(size_t)row * Dc + t * 8]) = z;
    *reinterpret_cast<float4*>(&al[(size_t)row * Dc + t * 8]) = z;
}

// ---------------------------------------------------------------------------
// Launch
// ---------------------------------------------------------------------------
extern "C" void kernel_launch(void* const* d_in, const int* in_sizes, int n_in,
                              void* d_out, int out_size) {
    (void)in_sizes; (void)n_in; (void)out_size;
    const float* x       = (const float*)d_in[0];
    const float* latents = (const float*)d_in[1];
    const float* t_emb   = (const float*)d_in[2];
    const int*   q_lens  = (const int*)  d_in[3];
    const int*   k_lens  = (const int*)  d_in[4];
    const float* ln_kv_w = (const float*)d_in[5];
    const float* ln_kv_b = (const float*)d_in[6];
    const float* ssg     = (const float*)d_in[7];
    const float* Wq      = (const float*)d_in[8];
    const float* bq      = (const float*)d_in[9];
    const float* Wkv     = (const float*)d_in[10];
    const float* bkv     = (const float*)d_in[11];
    const float* Wo      = (const float*)d_in[12];
    const float* bo      = (const float*)d_in[13];
    float* out = (float*)d_out;

    bf16 *xk_h, *xk_l, *lat_h, *lat_l, *q_h, *q_l, *kv_h, *kv_l;
    bf16 *p_h, *p_l, *at_h, *at_l, *wq_h, *wq_l, *wkv_h, *wkv_l, *wo_h, *wo_l;
    float* sc;
    cudaGetSymbolAddress((void**)&xk_h, g_xk_hi);   cudaGetSymbolAddress((void**)&xk_l, g_xk_lo);
    cudaGetSymbolAddress((void**)&lat_h, g_lat_hi); cudaGetSymbolAddress((void**)&lat_l, g_lat_lo);
    cudaGetSymbolAddress((void**)&q_h, g_q_hi);     cudaGetSymbolAddress((void**)&q_l, g_q_lo);
    cudaGetSymbolAddress((void**)&kv_h, g_kv_hi);   cudaGetSymbolAddress((void**)&kv_l, g_kv_lo);
    cudaGetSymbolAddress((void**)&p_h, g_p_hi);     cudaGetSymbolAddress((void**)&p_l, g_p_lo);
    cudaGetSymbolAddress((void**)&at_h, g_at_hi);   cudaGetSymbolAddress((void**)&at_l, g_at_lo);
    cudaGetSymbolAddress((void**)&wq_h, g_wq_hi);   cudaGetSymbolAddress((void**)&wq_l, g_wq_lo);
    cudaGetSymbolAddress((void**)&wkv_h, g_wkv_hi); cudaGetSymbolAddress((void**)&wkv_l, g_wkv_lo);
    cudaGetSymbolAddress((void**)&wo_h, g_wo_hi);   cudaGetSymbolAddress((void**)&wo_l, g_wo_lo);
    cudaGetSymbolAddress((void**)&sc, g_scores);

    // dynamic smem per instantiation (2 stages, BK=64)
    constexpr int SMEM_F256 = 2 * (2 * 128 * 72 * 2 + 2 * 64 * 264 * 2);  // 208896
    constexpr int SMEM_T256 = 2 * (2 * 128 * 72 * 2 + 2 * 256 * 72 * 2); // 221184
    constexpr int SMEM_F128 = 2 * (2 * 128 * 72 * 2 + 2 * 64 * 136 * 2);  // 143360
    cudaFuncSetAttribute(gemm_ks<false, 256, 1>, cudaFuncAttributeMaxDynamicSharedMemorySize, SMEM_F256);
    cudaFuncSetAttribute(gemm_ks<false, 256, 2>, cudaFuncAttributeMaxDynamicSharedMemorySize, SMEM_F256);
    cudaFuncSetAttribute(gemm_ks<true, 256, 0>,  cudaFuncAttributeMaxDynamicSharedMemorySize, SMEM_T256);
    cudaFuncSetAttribute(gemm_ks<false, 128, 1>, cudaFuncAttributeMaxDynamicSharedMemorySize, SMEM_F128);

    // Launch order keeps the kv GEMM at index 3 (the ncu capture slot).
    split_kernel<<<2048, 256>>>(Wkv, wkv_h, wkv_l, KVc * 2 * Dc / 4);          // 0
    ln_x_kernel<<<Bc * Kc, 256>>>(x, ln_kv_w, ln_kv_b, xk_h, xk_l);            // 1
    split_kernel<<<2048, 256>>>(Wq,  wq_h,  wq_l,  Dc * Dc / 4);               // 2

    // 3) kv = xk @ Wkv + bkv
    gemm_ks<false, 256, 1><<<dim3(2 * Dc / 256, (Bc * Kc) / 128, 1), 256, SMEM_F256>>>(
        xk_h, xk_l, wkv_h, wkv_l, nullptr, kv_h, kv_l, bkv, nullptr, nullptr,
        nullptr, 0,
        KVc, KVc, 2 * Dc, 2 * Dc, 0, 0, 0, 0, 0, 0, 1);

    ln_lat_kernel<<<Bc * Lc, 256>>>(latents, t_emb, ssg, lat_h, lat_l);        // 4

    // 5) q = lat @ Wq + bq
    gemm_ks<false, 256, 1><<<dim3(Dc / 256, (Bc * Lc) / 128, 1), 256, SMEM_F256>>>(
        lat_h, lat_l, wq_h, wq_l, nullptr, q_h, q_l, bq, nullptr, nullptr,
        nullptr, 0,
        Dc, Dc, Dc, Dc, 0, 0, 0, 0, 0, 0, 1);

    split_kernel<<<2048, 256>>>(Wo,  wo_h,  wo_l,  Dc * Dc / 4);               // 6

    // 7) scores[b,h] = q[b,:,h,:] @ k[b,:,h,:]^T  (skip fully-masked N tiles)
    gemm_ks<true, 256, 0><<<dim3(Kc / 256, Lc / 128, Bc * Hc), 256, SMEM_T256>>>(
        q_h, q_l, kv_h, kv_l, sc, nullptr, nullptr, nullptr, nullptr, nullptr,
        k_lens, 1,
        Cc, Dc, 2 * Dc, Kc,
        (long long)Lc * Dc, (long long)Cc,
        (long long)Kc * 2 * Dc, (long long)Cc,
        (long long)Hc * Lc * Kc, (long long)Lc * Kc, Hc);

    // 8) masked softmax -> p hi/lo
    softmax_kernel<<<Bc * Hc * Lc, 256>>>(sc, k_lens, p_h, p_l);

    // 9) attn_out = p @ v  (K-loop shortened to klen)
    gemm_ks<false, 128, 1><<<dim3(1, Lc / 128, Bc * Hc), 256, SMEM_F128>>>(
        p_h, p_l, kv_h + Dc, kv_l + Dc, nullptr, at_h, at_l, nullptr, nullptr, nullptr,
        k_lens, 2,
        Kc, Kc, 2 * Dc, Dc,
        (long long)Hc * Lc * Kc, (long long)Lc * Kc,
        (long long)Kc * 2 * Dc, (long long)Cc,
        (long long)Lc * Dc, (long long)Cc, Hc);

    // 10) qmask
    qmask_kernel<<<Bc * Lc, 256>>>(at_h, at_l, q_lens);

    // 11) out = (at @ Wo + bo) * gate
    gemm_ks<false, 256, 2><<<dim3(Dc / 256, (Bc * Lc) / 128, 1), 256, SMEM_F256>>>(
        at_h, at_l, wo_h, wo_l, out, nullptr, nullptr, bo, t_emb, ssg,
        nullptr, 0,
        Dc, Dc, Dc, Dc, 0, 0, 0, 0, 0, 0, 1);
}

// round 6
// speedup vs baseline: 1.4525x; 1.0014x over previous
#include <cuda_runtime.h>
#include <cuda_bf16.h>
#include <mma.h>
#include <cstdint>

using namespace nvcuda;
typedef __nv_bfloat16 bf16;

// Problem dims
constexpr int Bc  = 4;
constexpr int Lc  = 512;
constexpr int Dc  = 2048;
constexpr int Hc  = 16;
constexpr int Cc  = 128;
constexpr int KVc = 2048;
constexpr int Kc  = 1024;   // T*LA

// ---------------------------------------------------------------------------
// Scratch (device globals — allocation-free rule)
// ---------------------------------------------------------------------------
__device__ bf16  g_xk_hi[(size_t)Bc * Kc * KVc];
__device__ bf16  g_xk_lo[(size_t)Bc * Kc * KVc];
__device__ bf16  g_lat_hi[(size_t)Bc * Lc * Dc];
__device__ bf16  g_lat_lo[(size_t)Bc * Lc * Dc];
__device__ bf16  g_q_hi[(size_t)Bc * Lc * Dc];
__device__ bf16  g_q_lo[(size_t)Bc * Lc * Dc];
__device__ bf16  g_kv_hi[(size_t)Bc * Kc * 2 * Dc];
__device__ bf16  g_kv_lo[(size_t)Bc * Kc * 2 * Dc];
__device__ float g_scores[(size_t)Bc * Hc * Lc * Kc];
__device__ bf16  g_p_hi[(size_t)Bc * Hc * Lc * Kc];
__device__ bf16  g_p_lo[(size_t)Bc * Hc * Lc * Kc];
__device__ bf16  g_at_hi[(size_t)Bc * Lc * Dc];
__device__ bf16  g_at_lo[(size_t)Bc * Lc * Dc];
__device__ bf16  g_wq_hi[(size_t)Dc * Dc];
__device__ bf16  g_wq_lo[(size_t)Dc * Dc];
__device__ bf16  g_wkv_hi[(size_t)KVc * 2 * Dc];
__device__ bf16  g_wkv_lo[(size_t)KVc * 2 * Dc];
__device__ bf16  g_wo_hi[(size_t)Dc * Dc];
__device__ bf16  g_wo_lo[(size_t)Dc * Dc];

// ---------------------------------------------------------------------------
// Helpers
// ---------------------------------------------------------------------------
__device__ __forceinline__ void cp_async16(void* smem_dst, const void* gmem_src) {
    unsigned s = (unsigned)__cvta_generic_to_shared(smem_dst);
    asm volatile("cp.async.cg.shared.global [%0], [%1], 16;\n" :: "r"(s), "l"(gmem_src));
}
__device__ __forceinline__ void cp_commit() { asm volatile("cp.async.commit_group;\n"); }
__device__ __forceinline__ void cp_wait0()  { asm volatile("cp.async.wait_group 0;\n"); }
__device__ __forceinline__ void cp_wait1()  { asm volatile("cp.async.wait_group 1;\n"); }

struct __align__(8) bf4 { bf16 v[4]; };
__device__ __forceinline__ void split_store4(bf16* hi, bf16* lo, size_t off, float4 f) {
    bf4 H, L;
    float ff[4] = { f.x, f.y, f.z, f.w };
    #pragma unroll
    for (int e = 0; e < 4; e++) {
        bf16 h = __float2bfloat16(ff[e]);
        H.v[e] = h;
        L.v[e] = __float2bfloat16(ff[e] - __bfloat162float(h));
    }
    *reinterpret_cast<bf4*>(hi + off) = H;
    *reinterpret_cast<bf4*>(lo + off) = L;
}

__device__ __forceinline__ float warp_sum(float v) {
    #pragma unroll
    for (int o = 16; o > 0; o >>= 1) v += __shfl_xor_sync(0xffffffffu, v, o);
    return v;
}
__device__ __forceinline__ float warp_max(float v) {
    #pragma unroll
    for (int o = 16; o > 0; o >>= 1) v = fmaxf(v, __shfl_xor_sync(0xffffffffu, v, o));
    return v;
}
__device__ __forceinline__ float block_sum256(float v, float* red) {
    int lane = threadIdx.x & 31, w = threadIdx.x >> 5;
    v = warp_sum(v);
    if (lane == 0) red[w] = v;
    __syncthreads();
    if (w == 0) {
        float t = (lane < 8) ? red[lane] : 0.0f;
        t = warp_sum(t);
        if (lane == 0) red[32] = t;
    }
    __syncthreads();
    float r = red[32];
    __syncthreads();
    return r;
}
__device__ __forceinline__ float block_max256(float v, float* red) {
    int lane = threadIdx.x & 31, w = threadIdx.x >> 5;
    v = warp_max(v);
    if (lane == 0) red[w] = v;
    __syncthreads();
    if (w == 0) {
        float t = (lane < 8) ? red[lane] : -1e30f;
        t = warp_max(t);
        if (lane == 0) red[32] = t;
    }
    __syncthreads();
    float r = red[32];
    __syncthreads();
    return r;
}

// ---------------------------------------------------------------------------
// fp32 -> bf16 hi/lo splitter (weights)
// ---------------------------------------------------------------------------
__global__ void split_kernel(const float* __restrict__ W,
                             bf16* __restrict__ hi, bf16* __restrict__ lo,
                             int total4) {
    int i = blockIdx.x * blockDim.x + threadIdx.x;
    const int stride = gridDim.x * blockDim.x;
    for (; i < total4; i += stride) {
        float4 v = reinterpret_cast<const float4*>(W)[i];
        split_store4(hi, lo, (size_t)i * 4, v);
    }
}

// ---------------------------------------------------------------------------
// bf16x3 GEMM, pre-split operands, BK=64, 2-stage cp.async double buffer.
//   BCOL=false: C = A @ B       (B row-major Kd x N)
//   BCOL=true : C = A @ B^T     (B row-major N x Kd)
// CTA tile 128 x BN, 256 threads, 8 warps (2 x 4): warp tile 64 x (BN/4).
// Inner loop is term-outer / i-inner so consecutive MMAs never share an
// accumulator (RAW reuse distance = 4 wmma = 8 HMMA).
// OMODE: 0 fp32 store; 1 bf16 hi/lo (+bias); 2 (acc+bias)*gate fp32.
// kmode: 0 none; 1 skip CTA if n0 >= k_lens[b]; 2 shorten K to k_lens[b].
// ---------------------------------------------------------------------------
template <bool BCOL, int BN, int OMODE>
__global__ void __launch_bounds__(256)
gemm_ks(const bf16* __restrict__ Ah, const bf16* __restrict__ Al,
        const bf16* __restrict__ Bh, const bf16* __restrict__ Bl,
        float* __restrict__ C, bf16* __restrict__ Ch, bf16* __restrict__ Cl,
        const float* __restrict__ bias,
        const float* __restrict__ t_emb, const float* __restrict__ ssg,
        const int* __restrict__ klens, int kmode,
        int Kd, int lda, int ldb, int ldc,
        long long asb, long long ash,
        long long bsb, long long bsh,
        long long csb, long long csh, int HB) {
    extern __shared__ char sm[];
    constexpr int APITCH = 72;                       // bf16 pitch, BK=64 (+8 pad)
    constexpr int BPITCH = BCOL ? 72 : (BN + 8);
    constexpr int ABYTES = 128 * APITCH * 2;         // 18432 per A slice
    constexpr int BBYTES = BCOL ? BN * 72 * 2 : 64 * (BN + 8) * 2;
    constexpr int STAGE  = 2 * ABYTES + 2 * BBYTES;
    constexpr int WN     = BN / 64;                  // wmma j-tiles per warp

    const int z  = blockIdx.z;
    const int bb = z / HB, hh = z - bb * HB;
    const int n0 = blockIdx.x * BN;
    const int m0 = blockIdx.y * 128;

    if (kmode == 1 && klens && n0 >= klens[bb]) return;  // fully masked tile

    Ah += (size_t)bb * asb + (size_t)hh * ash;
    Al += (size_t)bb * asb + (size_t)hh * ash;
    Bh += (size_t)bb * bsb + (size_t)hh * bsh;
    Bl += (size_t)bb * bsb + (size_t)hh * bsh;
    const long long coff = (long long)bb * csb + (long long)hh * csh;
    if (OMODE == 0 || OMODE == 2) C += coff; else { Ch += coff; Cl += coff; }

    const int tid  = threadIdx.x;
    const int warp = tid >> 5;
    const int lane = tid & 31;
    const int wm   = warp & 1;
    const int wn   = warp >> 1;

    wmma::fragment<wmma::accumulator, 16, 16, 16, float> acc[4][WN];
    #pragma unroll
    for (int i = 0; i < 4; i++)
        #pragma unroll
        for (int j = 0; j < WN; j++) wmma::fill_fragment(acc[i][j], 0.0f);

    auto load_stage = [&](int st, int k0) {
        char* base = sm + st * STAGE;
        bf16* dAh = (bf16*)base;
        bf16* dAl = (bf16*)(base + ABYTES);
        bf16* dBh = (bf16*)(base + 2 * ABYTES);
        bf16* dBl = (bf16*)(base + 2 * ABYTES + BBYTES);
        // A hi+lo: 128 rows x 64 cols -> 1024 16B-chunks per array
        #pragma unroll
        for (int i = 0; i < 8; i++) {
            int idx = tid + (i << 8);
            int l = idx & 1023;
            int r = l >> 3, c = (l & 7) * 8;
            const bf16* src = (idx < 1024 ? Ah : Al) + (size_t)(m0 + r) * lda + k0 + c;
            cp_async16((idx < 1024 ? dAh : dAl) + r * APITCH + c, src);
        }
        if constexpr (BCOL) {
            // B hi+lo: BN rows x 64 cols
            #pragma unroll
            for (int i = 0; i < BN / 16; i++) {
                int idx = tid + (i << 8);
                int l = idx & (BN * 8 - 1);
                int r = l >> 3, c = (l & 7) * 8;
                const bf16* src = (idx < BN * 8 ? Bh : Bl) + (size_t)(n0 + r) * ldb + k0 + c;
                cp_async16((idx < BN * 8 ? dBh : dBl) + r * APITCH + c, src);
            }
        } else {
            // B hi+lo: 64 rows x BN cols
            constexpr int CPR = BN / 8;              // 16B chunks per row
            #pragma unroll
            for (int i = 0; i < BN / 16; i++) {
                int idx = tid + (i << 8);
                int l = idx & (8 * BN - 1);
                int r = l / CPR, c = (l % CPR) * 8;
                const bf16* src = (idx < 8 * BN ? Bh : Bl) + (size_t)(k0 + r) * ldb + n0 + c;
                cp_async16((idx < 8 * BN ? dBh : dBl) + r * BPITCH + c, src);
            }
        }
    };

    int nIter = Kd >> 6;
    if (kmode == 2 && klens) {
        int kl = klens[bb];
        int ni = (kl + 63) >> 6;
        if (ni < nIter) nIter = ni;
    }

    load_stage(0, 0); cp_commit();
    if (nIter > 1) { load_stage(1, 64); cp_commit(); }

    for (int it = 0; it < nIter; ++it) {
        if (it + 1 < nIter) cp_wait1(); else cp_wait0();
        __syncthreads();

        char* base = sm + (it & 1) * STAGE;
        const bf16* sAh = (const bf16*)base;
        const bf16* sAl = (const bf16*)(base + ABYTES);
        const bf16* sBh = (const bf16*)(base + 2 * ABYTES);
        const bf16* sBl = (const bf16*)(base + 2 * ABYTES + BBYTES);
        #pragma unroll
        for (int kk = 0; kk < 4; kk++) {
            wmma::fragment<wmma::matrix_a, 16, 16, 16, bf16, wmma::row_major> ah[4], al[4];
            #pragma unroll
            for (int i = 0; i < 4; i++) {
                wmma::load_matrix_sync(ah[i], sAh + (wm * 64 + 16 * i) * APITCH + kk * 16, APITCH);
                wmma::load_matrix_sync(al[i], sAl + (wm * 64 + 16 * i) * APITCH + kk * 16, APITCH);
            }
            #pragma unroll
            for (int j = 0; j < WN; j++) {
                const int ncol = wn * (BN / 4) + 16 * j;
                if constexpr (BCOL) {
                    wmma::fragment<wmma::matrix_b, 16, 16, 16, bf16, wmma::col_major> bh, bl;
                    wmma::load_matrix_sync(bh, sBh + ncol * APITCH + kk * 16, APITCH);
                    wmma::load_matrix_sync(bl, sBl + ncol * APITCH + kk * 16, APITCH);
                    // term-outer / i-inner: no back-to-back RAW on any acc
                    #pragma unroll
                    for (int i = 0; i < 4; i++) wmma::mma_sync(acc[i][j], ah[i], bh, acc[i][j]);
                    #pragma unroll
                    for (int i = 0; i < 4; i++) wmma::mma_sync(acc[i][j], al[i], bh, acc[i][j]);
                    #pragma unroll
                    for (int i = 0; i < 4; i++) wmma::mma_sync(acc[i][j], ah[i], bl, acc[i][j]);
                } else {
                    wmma::fragment<wmma::matrix_b, 16, 16, 16, bf16, wmma::row_major> bh, bl;
                    wmma::load_matrix_sync(bh, sBh + (kk * 16) * BPITCH + ncol, BPITCH);
                    wmma::load_matrix_sync(bl, sBl + (kk * 16) * BPITCH + ncol, BPITCH);
                    #pragma unroll
                    for (int i = 0; i < 4; i++) wmma::mma_sync(acc[i][j], ah[i], bh, acc[i][j]);
                    #pragma unroll
                    for (int i = 0; i < 4; i++) wmma::mma_sync(acc[i][j], al[i], bh, acc[i][j]);
                    #pragma unroll
                    for (int i = 0; i < 4; i++) wmma::mma_sync(acc[i][j], ah[i], bl, acc[i][j]);
                }
            }
        }

        if (it + 2 < nIter) {
            __syncthreads();                 // all warps done reading buffer (it&1)
            load_stage(it & 1, (it + 2) << 6);
            cp_commit();
        }
    }

    if constexpr (OMODE == 0) {
        #pragma unroll
        for (int i = 0; i < 4; i++)
            #pragma unroll
            for (int j = 0; j < WN; j++)
                wmma::store_matrix_sync(
                    C + (size_t)(m0 + wm * 64 + 16 * i) * ldc + n0 + wn * (BN / 4) + 16 * j,
                    acc[i][j], ldc, wmma::mem_row_major);
    } else {
        __syncthreads();
        float* stag = (float*)sm + warp * 2560;  // 64 x 40 floats per warp
        const int bidx = m0 / Lc;
        #pragma unroll
        for (int p = 0; p < WN / 2; p++) {
            #pragma unroll
            for (int i = 0; i < 4; i++)
                #pragma unroll
                for (int jj = 0; jj < 2; jj++)
                    wmma::store_matrix_sync(stag + (16 * i) * 40 + 16 * jj,
                                            acc[i][2 * p + jj], 40, wmma::mem_row_major);
            __syncwarp();
            #pragma unroll
            for (int itr = 0; itr < 16; itr++) {
                int g = lane + itr * 32;
                int r = g >> 3;
                int c = (g & 7) * 4;
                float4 v = *reinterpret_cast<const float4*>(stag + r * 40 + c);
                int gr = m0 + wm * 64 + r;
                int gc = n0 + wn * (BN / 4) + p * 32 + c;
                if constexpr (OMODE == 1) {
                    if (bias) {
                        float4 bv = *reinterpret_cast<const float4*>(&bias[gc]);
                        v.x += bv.x; v.y += bv.y; v.z += bv.z; v.w += bv.w;
                    }
                    split_store4(Ch, Cl, (size_t)gr * ldc + gc, v);
                } else {
                    float4 bv = *reinterpret_cast<const float4*>(&bias[gc]);
                    float4 g1 = *reinterpret_cast<const float4*>(&t_emb[(size_t)(bidx * 3 + 2) * Dc + gc]);
                    float4 g2 = *reinterpret_cast<const float4*>(&ssg[2 * Dc + gc]);
                    float4 o;
                    o.x = (v.x + bv.x) * (g1.x + g2.x);
                    o.y = (v.y + bv.y) * (g1.y + g2.y);
                    o.z = (v.z + bv.z) * (g1.z + g2.z);
                    o.w = (v.w + bv.w) * (g1.w + g2.w);
                    *reinterpret_cast<float4*>(&C[(size_t)gr * ldc + gc]) = o;
                }
            }
            __syncwarp();
        }
    }
}

// ---------------------------------------------------------------------------
// LayerNorm of x -> xk hi/lo
// ---------------------------------------------------------------------------
__global__ void ln_x_kernel(const float* __restrict__ x,
                            const float* __restrict__ w,
                            const float* __restrict__ b,
                            bf16* __restrict__ out_hi, bf16* __restrict__ out_lo) {
    __shared__ float red[33];
    const int row = blockIdx.x;
    const size_t base = (size_t)row * KVc;
    const int t = threadIdx.x;
    const int c0 = t * 4, c1 = c0 + 1024;

    float4 v0 = *reinterpret_cast<const float4*>(&x[base + c0]);
    float4 v1 = *reinterpret_cast<const float4*>(&x[base + c1]);
    float s = v0.x + v0.y + v0.z + v0.w + v1.x + v1.y + v1.z + v1.w;
    float mean = block_sum256(s, red) * (1.0f / KVc);
    float d0x = v0.x - mean, d0y = v0.y - mean, d0z = v0.z - mean, d0w = v0.w - mean;
    float d1x = v1.x - mean, d1y = v1.y - mean, d1z = v1.z - mean, d1w = v1.w - mean;
    float sq = d0x*d0x + d0y*d0y + d0z*d0z + d0w*d0w + d1x*d1x + d1y*d1y + d1z*d1z + d1w*d1w;
    float var = block_sum256(sq, red) * (1.0f / KVc);
    float rstd = rsqrtf(var + 1e-5f);

    float4 w0 = *reinterpret_cast<const float4*>(&w[c0]);
    float4 w1 = *reinterpret_cast<const float4*>(&w[c1]);
    float4 b0 = *reinterpret_cast<const float4*>(&b[c0]);
    float4 b1 = *reinterpret_cast<const float4*>(&b[c1]);
    split_store4(out_hi, out_lo, base + c0,
        make_float4(d0x*rstd*w0.x + b0.x, d0y*rstd*w0.y + b0.y,
                    d0z*rstd*w0.z + b0.z, d0w*rstd*w0.w + b0.w));
    split_store4(out_hi, out_lo, base + c1,
        make_float4(d1x*rstd*w1.x + b1.x, d1y*rstd*w1.y + b1.y,
                    d1z*rstd*w1.z + b1.z, d1w*rstd*w1.w + b1.w));
}

// ---------------------------------------------------------------------------
// LayerNorm of latents + adaLN modulation -> lat hi/lo
// ---------------------------------------------------------------------------
__global__ void ln_lat_kernel(const float* __restrict__ latents,
                              const float* __restrict__ t_emb,
                              const float* __restrict__ ssg,
                              bf16* __restrict__ out_hi, bf16* __restrict__ out_lo) {
    __shared__ float red[33];
    const int row = blockIdx.x;
    const int bidx = row / Lc;
    const size_t base = (size_t)row * Dc;
    const int t = threadIdx.x;
    const int c0 = t * 4, c1 = c0 + 1024;

    float4 v0 = *reinterpret_cast<const float4*>(&latents[base + c0]);
    float4 v1 = *reinterpret_cast<const float4*>(&latents[base + c1]);
    float s = v0.x + v0.y + v0.z + v0.w + v1.x + v1.y + v1.z + v1.w;
    float mean = block_sum256(s, red) * (1.0f / Dc);
    float d0x = v0.x - mean, d0y = v0.y - mean, d0z = v0.z - mean, d0w = v0.w - mean;
    float d1x = v1.x - mean, d1y = v1.y - mean, d1z = v1.z - mean, d1w = v1.w - mean;
    float sq = d0x*d0x + d0y*d0y + d0z*d0z + d0w*d0w + d1x*d1x + d1y*d1y + d1z*d1z + d1w*d1w;
    float var = block_sum256(sq, red) * (1.0f / Dc);
    float rstd = rsqrtf(var + 1e-5f);

    const float* sh_t = t_emb + (size_t)(bidx * 3 + 0) * Dc;
    const float* sc_t = t_emb + (size_t)(bidx * 3 + 1) * Dc;

    #pragma unroll
    for (int half = 0; half < 2; half++) {
        int c = (half == 0) ? c0 : c1;
        float dv[4] = { (half ? d1x : d0x), (half ? d1y : d0y),
                        (half ? d1z : d0z), (half ? d1w : d0w) };
        float4 sht = *reinterpret_cast<const float4*>(&sh_t[c]);
        float4 sct = *reinterpret_cast<const float4*>(&sc_t[c]);
        float4 shs = *reinterpret_cast<const float4*>(&ssg[c]);
        float4 scs = *reinterpret_cast<const float4*>(&ssg[Dc + c]);
        float4 o;
        o.x = dv[0]*rstd * (1.0f + sct.x + scs.x) + sht.x + shs.x;
        o.y = dv[1]*rstd * (1.0f + sct.y + scs.y) + sht.y + shs.y;
        o.z = dv[2]*rstd * (1.0f + sct.z + scs.z) + sht.z + shs.z;
        o.w = dv[3]*rstd * (1.0f + sct.w + scs.w) + sht.w + shs.w;
        split_store4(out_hi, out_lo, base + c, o);
    }
}

// ---------------------------------------------------------------------------
// Masked softmax over K=1024; alpha on read; writes bf16 hi/lo probabilities.
// ---------------------------------------------------------------------------
__global__ void softmax_kernel(const float* __restrict__ sc,
                               const int* __restrict__ k_lens,
                               bf16* __restrict__ ph, bf16* __restrict__ pl) {
    __shared__ float red[33];
    const int row = blockIdx.x;
    const int bidx = row / (Hc * Lc);
    const int klen = k_lens[bidx];
    const float* p = sc + (size_t)row * Kc;
    const int t = threadIdx.x;
    const int j0 = t * 4;
    const float alpha = 0.08838834764831845f;

    float4 v = *reinterpret_cast<const float4*>(&p[j0]);
    float vv[4] = { v.x, v.y, v.z, v.w };
    float mx = -1e30f;
    #pragma unroll
    for (int i = 0; i < 4; i++) {
        vv[i] = (j0 + i < klen) ? vv[i] * alpha : -1e30f;
        mx = fmaxf(mx, vv[i]);
    }
    mx = block_max256(mx, red);
    float e[4]; float s = 0.0f;
    #pragma unroll
    for (int i = 0; i < 4; i++) {
        e[i] = (j0 + i < klen) ? expf(vv[i] - mx) : 0.0f;
        s += e[i];
    }
    s = block_sum256(s, red);
    float inv = 1.0f / s;
    split_store4(ph, pl, (size_t)row * Kc + j0,
                 make_float4(e[0] * inv, e[1] * inv, e[2] * inv, e[3] * inv));
}

// ---------------------------------------------------------------------------
// Zero attention-output rows where l >= q_lens[b]
// ---------------------------------------------------------------------------
__global__ void qmask_kernel(bf16* __restrict__ ah, bf16* __restrict__ al,
                             const int* __restrict__ q_lens) {
    const int row = blockIdx.x;
    const int bidx = row / Lc;
    const int l = row - bidx * Lc;
    if (l < q_lens[bidx]) return;
    const int t = threadIdx.x;
    float4 z = make_float4(0.f, 0.f, 0.f, 0.f);
    *reinterpret_cast<float4*>(&ah[(size_t)row * Dc + t * 8]) = z;
    *reinterpret_cast<float4*>(&al[(size_t)row * Dc + t * 8]) = z;
}

// ---------------------------------------------------------------------------
// Launch
// ---------------------------------------------------------------------------
extern "C" void kernel_launch(void* const* d_in, const int* in_sizes, int n_in,
                              void* d_out, int out_size) {
    (void)in_sizes; (void)n_in; (void)out_size;
    const float* x       = (const float*)d_in[0];
    const float* latents = (const float*)d_in[1];
    const float* t_emb   = (const float*)d_in[2];
    const int*   q_lens  = (const int*)  d_in[3];
    const int*   k_lens  = (const int*)  d_in[4];
    const float* ln_kv_w = (const float*)d_in[5];
    const float* ln_kv_b = (const float*)d_in[6];
    const float* ssg     = (const float*)d_in[7];
    const float* Wq      = (const float*)d_in[8];
    const float* bq      = (const float*)d_in[9];
    const float* Wkv     = (const float*)d_in[10];
    const float* bkv     = (const float*)d_in[11];
    const float* Wo      = (const float*)d_in[12];
    const float* bo      = (const float*)d_in[13];
    float* out = (float*)d_out;

    bf16 *xk_h, *xk_l, *lat_h, *lat_l, *q_h, *q_l, *kv_h, *kv_l;
    bf16 *p_h, *p_l, *at_h, *at_l, *wq_h, *wq_l, *wkv_h, *wkv_l, *wo_h, *wo_l;
    float* sc;
    cudaGetSymbolAddress((void**)&xk_h, g_xk_hi);   cudaGetSymbolAddress((void**)&xk_l, g_xk_lo);
    cudaGetSymbolAddress((void**)&lat_h, g_lat_hi); cudaGetSymbolAddress((void**)&lat_l, g_lat_lo);
    cudaGetSymbolAddress((void**)&q_h, g_q_hi);     cudaGetSymbolAddress((void**)&q_l, g_q_lo);
    cudaGetSymbolAddress((void**)&kv_h, g_kv_hi);   cudaGetSymbolAddress((void**)&kv_l, g_kv_lo);
    cudaGetSymbolAddress((void**)&p_h, g_p_hi);     cudaGetSymbolAddress((void**)&p_l, g_p_lo);
    cudaGetSymbolAddress((void**)&at_h, g_at_hi);   cudaGetSymbolAddress((void**)&at_l, g_at_lo);
    cudaGetSymbolAddress((void**)&wq_h, g_wq_hi);   cudaGetSymbolAddress((void**)&wq_l, g_wq_lo);
    cudaGetSymbolAddress((void**)&wkv_h, g_wkv_hi); cudaGetSymbolAddress((void**)&wkv_l, g_wkv_lo);
    cudaGetSymbolAddress((void**)&wo_h, g_wo_hi);   cudaGetSymbolAddress((void**)&wo_l, g_wo_lo);
    cudaGetSymbolAddress((void**)&sc, g_scores);

    // dynamic smem per instantiation (2 stages, BK=64)
    constexpr int SMEM_F256 = 2 * (2 * 128 * 72 * 2 + 2 * 64 * 264 * 2);  // 208896
    constexpr int SMEM_T256 = 2 * (2 * 128 * 72 * 2 + 2 * 256 * 72 * 2); // 221184
    constexpr int SMEM_F128 = 2 * (2 * 128 * 72 * 2 + 2 * 64 * 136 * 2);  // 143360
    cudaFuncSetAttribute(gemm_ks<false, 256, 1>, cudaFuncAttributeMaxDynamicSharedMemorySize, SMEM_F256);
    cudaFuncSetAttribute(gemm_ks<false, 256, 2>, cudaFuncAttributeMaxDynamicSharedMemorySize, SMEM_F256);
    cudaFuncSetAttribute(gemm_ks<true, 256, 0>,  cudaFuncAttributeMaxDynamicSharedMemorySize, SMEM_T256);
    cudaFuncSetAttribute(gemm_ks<false, 128, 1>, cudaFuncAttributeMaxDynamicSharedMemorySize, SMEM_F128);

    // Launch order keeps the kv GEMM at index 3 (the ncu capture slot).
    split_kernel<<<2048, 256>>>(Wkv, wkv_h, wkv_l, KVc * 2 * Dc / 4);          // 0
    ln_x_kernel<<<Bc * Kc, 256>>>(x, ln_kv_w, ln_kv_b, xk_h, xk_l);            // 1
    split_kernel<<<2048, 256>>>(Wq,  wq_h,  wq_l,  Dc * Dc / 4);               // 2

    // 3) kv = xk @ Wkv + bkv
    gemm_ks<false, 256, 1><<<dim3(2 * Dc / 256, (Bc * Kc) / 128, 1), 256, SMEM_F256>>>(
        xk_h, xk_l, wkv_h, wkv_l, nullptr, kv_h, kv_l, bkv, nullptr, nullptr,
        nullptr, 0,
        KVc, KVc, 2 * Dc, 2 * Dc, 0, 0, 0, 0, 0, 0, 1);

    ln_lat_kernel<<<Bc * Lc, 256>>>(latents, t_emb, ssg, lat_h, lat_l);        // 4

    // 5) q = lat @ Wq + bq
    gemm_ks<false, 256, 1><<<dim3(Dc / 256, (Bc * Lc) / 128, 1), 256, SMEM_F256>>>(
        lat_h, lat_l, wq_h, wq_l, nullptr, q_h, q_l, bq, nullptr, nullptr,
        nullptr, 0,
        Dc, Dc, Dc, Dc, 0, 0, 0, 0, 0, 0, 1);

    split_kernel<<<2048, 256>>>(Wo,  wo_h,  wo_l,  Dc * Dc / 4);               // 6

    // 7) scores[b,h] = q[b,:,h,:] @ k[b,:,h,:]^T  (skip fully-masked N tiles)
    gemm_ks<true, 256, 0><<<dim3(Kc / 256, Lc / 128, Bc * Hc), 256, SMEM_T256>>>(
        q_h, q_l, kv_h, kv_l, sc, nullptr, nullptr, nullptr, nullptr, nullptr,
        k_lens, 1,
        Cc, Dc, 2 * Dc, Kc,
        (long long)Lc * Dc, (long long)Cc,
        (long long)Kc * 2 * Dc, (long long)Cc,
        (long long)Hc * Lc * Kc, (long long)Lc * Kc, Hc);

    // 8) masked softmax -> p hi/lo
    softmax_kernel<<<Bc * Hc * Lc, 256>>>(sc, k_lens, p_h, p_l);

    // 9) attn_out = p @ v  (K-loop shortened to klen)
    gemm_ks<false, 128, 1><<<dim3(1, Lc / 128, Bc * Hc), 256, SMEM_F128>>>(
        p_h, p_l, kv_h + Dc, kv_l + Dc, nullptr, at_h, at_l, nullptr, nullptr, nullptr,
        k_lens, 2,
        Kc, Kc, 2 * Dc, Dc,
        (long long)Hc * Lc * Kc, (long long)Lc * Kc,
        (long long)Kc * 2 * Dc, (long long)Cc,
        (long long)Lc * Dc, (long long)Cc, Hc);

    // 10) qmask
    qmask_kernel<<<Bc * Lc, 256>>>(at_h, at_l, q_lens);

    // 11) out = (at @ Wo + bo) * gate
    gemm_ks<false, 256, 2><<<dim3(Dc / 256, (Bc * Lc) / 128, 1), 256, SMEM_F256>>>(
        at_h, at_l, wo_h, wo_l, out, nullptr, nullptr, bo, t_emb, ssg,
        nullptr, 0,
        Dc, Dc, Dc, Dc, 0, 0, 0, 0, 0, 0, 1);
}